// round 12
// baseline (speedup 1.0000x reference)
#include <cuda_runtime.h>
#include <cuda_bf16.h>

#define NN   20000
#define INCH 256
#define HEADS 8
#define HID  32
#define C1   256      // HEADS*HID
#define OUTC 40
#define E0   320000
#define ET   340000   // + self loops
#define NEG  0.2f

// ---------------- scratch (device globals; no allocation allowed) ----------
__device__ __nv_bfloat16 g_h1[NN * C1];    // x @ W1 (bf16)
__device__ float g_as1[NN * HEADS];
__device__ float g_ad1[NN * HEADS];
__device__ __nv_bfloat16 g_out1[NN * C1];  // elu(aggr + b1) (bf16)
__device__ __nv_bfloat16 g_h2[NN * OUTC];  // out1 @ W2 (bf16)
__device__ float g_as2[NN];
__device__ float g_ad2[NN];
__device__ int   g_deg[NN];                // zero-init at load; re-zeroed by scan
__device__ int   g_off[NN + 1];
__device__ int   g_cur[NN];
__device__ int   g_src[ET];                // CSR payload: src node per slot

// ---------------- helpers ---------------------------------------------------
__device__ __forceinline__ unsigned f2tf32(float f) {
    unsigned r;
    asm volatile("cvt.rna.tf32.f32 %0, %1;" : "=r"(r) : "f"(f));
    return r;
}
__device__ __forceinline__ void mma_tf32(float* c, const unsigned* a, unsigned b0, unsigned b1) {
    asm volatile(
        "mma.sync.aligned.m16n8k8.row.col.f32.tf32.tf32.f32 "
        "{%0,%1,%2,%3}, {%4,%5,%6,%7}, {%8,%9}, {%0,%1,%2,%3};"
        : "+f"(c[0]), "+f"(c[1]), "+f"(c[2]), "+f"(c[3])
        : "r"(a[0]), "r"(a[1]), "r"(a[2]), "r"(a[3]), "r"(b0), "r"(b1));
}
__device__ __forceinline__ float lrelu_exp(float v) {
    v = v > 0.f ? v : NEG * v;
    return __expf(v);
}
__device__ __forceinline__ unsigned pack_bf2(float a, float b) {
    __nv_bfloat162 t = __floats2bfloat162_rn(a, b);
    return *reinterpret_cast<unsigned*>(&t);
}

// ---------------- CSR build --------------------------------------------------
__global__ void deg_hist(const int* __restrict__ ei) {
    int e = blockIdx.x * blockDim.x + threadIdx.x;
    if (e >= E0) return;
    atomicAdd(&g_deg[ei[E0 + e]], 1);
}

// single-block exclusive scan over (g_deg+1); pre-places self-loop at slot 0;
// re-zeroes g_deg so the next graph replay starts from a clean histogram.
__global__ __launch_bounds__(1024) void scan_kernel() {
    __shared__ int wsum[32];
    __shared__ int carry_s;
    int tid = threadIdx.x;
    int lane = tid & 31, wid = tid >> 5;
    if (tid == 0) carry_s = 0;
    __syncthreads();
    for (int base = 0; base < NN; base += 1024) {
        int idx = base + tid;
        int v = 0;
        if (idx < NN) {
            v = g_deg[idx] + 1;     // +1 = self-loop
            g_deg[idx] = 0;          // reset for next replay
        }
        int x = v;
#pragma unroll
        for (int o = 1; o < 32; o <<= 1) {
            int y = __shfl_up_sync(~0u, x, o);
            if (lane >= o) x += y;
        }
        if (lane == 31) wsum[wid] = x;
        __syncthreads();
        if (wid == 0) {
            int w = wsum[lane];
#pragma unroll
            for (int o = 1; o < 32; o <<= 1) {
                int y = __shfl_up_sync(~0u, w, o);
                if (lane >= o) w += y;
            }
            wsum[lane] = w;
        }
        __syncthreads();
        int incl = x + (wid ? wsum[wid - 1] : 0);
        int excl = carry_s + incl - v;
        if (idx < NN) {
            g_off[idx] = excl;
            g_cur[idx] = excl + 1;   // slot 0 taken by self-loop
            g_src[excl] = idx;       // self-loop
        }
        __syncthreads();
        if (tid == 0) carry_s += wsum[31];
        __syncthreads();
    }
    if (tid == 0) g_off[NN] = carry_s;
}

__global__ void fill_csr(const int* __restrict__ ei) {
    int e = blockIdx.x * blockDim.x + threadIdx.x;
    if (e >= E0) return;
    int s = ei[e];
    int d = ei[E0 + e];
    int pos = atomicAdd(&g_cur[d], 1);
    g_src[pos] = s;
}

// ---------------- GEMM1: h1 = x @ W1 (tf32, pipelined) + fused alpha1 -------
__global__ __launch_bounds__(256) void gemm1_kernel(const float* __restrict__ x,
                                                    const float* __restrict__ W1,
                                                    const float* __restrict__ a1s,
                                                    const float* __restrict__ a1d) {
    __shared__ float As[128][36];
    __shared__ float Bs[32][136];
    int tid = threadIdx.x;
    int lane = tid & 31, wid = tid >> 5;
    int wm = wid & 3, wn = wid >> 2;
    int g = lane >> 2, tg = lane & 3;
    int m0 = blockIdx.y * 128, n0 = blockIdx.x * 128;

    float acc[2][8][4];
#pragma unroll
    for (int i = 0; i < 2; i++)
#pragma unroll
        for (int j = 0; j < 8; j++)
#pragma unroll
            for (int k = 0; k < 4; k++) acc[i][j][k] = 0.f;

    int a_r = tid >> 3;
    int a_c = (tid & 7) * 4;
    int b_r = tid >> 3;
    int b_c0 = tid & 7;

    float4 pa[4], pb[4];
#pragma unroll
    for (int j = 0; j < 4; j++) {
        int gm = m0 + a_r + 32 * j;
        pa[j] = make_float4(0.f, 0.f, 0.f, 0.f);
        if (gm < NN) pa[j] = *reinterpret_cast<const float4*>(&x[(size_t)gm * INCH + a_c]);
        pb[j] = *reinterpret_cast<const float4*>(&W1[(size_t)b_r * C1 + n0 + (b_c0 + 8 * j) * 4]);
    }

    for (int k0 = 0; k0 < INCH; k0 += 32) {
#pragma unroll
        for (int j = 0; j < 4; j++) {
            int r = a_r + 32 * j;
            As[r][a_c + 0] = __uint_as_float(f2tf32(pa[j].x));
            As[r][a_c + 1] = __uint_as_float(f2tf32(pa[j].y));
            As[r][a_c + 2] = __uint_as_float(f2tf32(pa[j].z));
            As[r][a_c + 3] = __uint_as_float(f2tf32(pa[j].w));
            int c = (b_c0 + 8 * j) * 4;
            Bs[b_r][c + 0] = __uint_as_float(f2tf32(pb[j].x));
            Bs[b_r][c + 1] = __uint_as_float(f2tf32(pb[j].y));
            Bs[b_r][c + 2] = __uint_as_float(f2tf32(pb[j].z));
            Bs[b_r][c + 3] = __uint_as_float(f2tf32(pb[j].w));
        }
        __syncthreads();
        int kn = k0 + 32;
        if (kn < INCH) {
#pragma unroll
            for (int j = 0; j < 4; j++) {
                int gm = m0 + a_r + 32 * j;
                pa[j] = make_float4(0.f, 0.f, 0.f, 0.f);
                if (gm < NN) pa[j] = *reinterpret_cast<const float4*>(&x[(size_t)gm * INCH + kn + a_c]);
                pb[j] = *reinterpret_cast<const float4*>(&W1[(size_t)(kn + b_r) * C1 + n0 + (b_c0 + 8 * j) * 4]);
            }
        }
#pragma unroll
        for (int ks = 0; ks < 4; ks++) {
            int kk = ks * 8;
            unsigned a[2][4];
#pragma unroll
            for (int mi = 0; mi < 2; mi++) {
                int rb = wm * 32 + mi * 16 + g;
                a[mi][0] = __float_as_uint(As[rb][kk + tg]);
                a[mi][1] = __float_as_uint(As[rb + 8][kk + tg]);
                a[mi][2] = __float_as_uint(As[rb][kk + tg + 4]);
                a[mi][3] = __float_as_uint(As[rb + 8][kk + tg + 4]);
            }
#pragma unroll
            for (int nt = 0; nt < 8; nt++) {
                int col = wn * 64 + nt * 8 + g;
                unsigned b0 = __float_as_uint(Bs[kk + tg][col]);
                unsigned b1 = __float_as_uint(Bs[kk + tg + 4][col]);
                mma_tf32(acc[0][nt], a[0], b0, b1);
                mma_tf32(acc[1][nt], a[1], b0, b1);
            }
        }
        __syncthreads();
    }

    // epilogue: store h1 (bf16) + fused alpha1 partials (fp32)
    float ps[2][2][2] = {}, pd[2][2][2] = {};
#pragma unroll
    for (int mi = 0; mi < 2; mi++) {
        int r = m0 + wm * 32 + mi * 16 + g;
#pragma unroll
        for (int nt = 0; nt < 8; nt++) {
            int c = n0 + wn * 64 + nt * 8 + tg * 2;
            int hl = nt >> 2;
            float w0s = a1s[c], w1s = a1s[c + 1];
            float w0d = a1d[c], w1d = a1d[c + 1];
            if (r < NN) {
                *reinterpret_cast<__nv_bfloat162*>(&g_h1[(size_t)r * C1 + c]) =
                    __floats2bfloat162_rn(acc[mi][nt][0], acc[mi][nt][1]);
            }
            if (r + 8 < NN) {
                *reinterpret_cast<__nv_bfloat162*>(&g_h1[(size_t)(r + 8) * C1 + c]) =
                    __floats2bfloat162_rn(acc[mi][nt][2], acc[mi][nt][3]);
            }
            ps[mi][0][hl] += acc[mi][nt][0] * w0s + acc[mi][nt][1] * w1s;
            ps[mi][1][hl] += acc[mi][nt][2] * w0s + acc[mi][nt][3] * w1s;
            pd[mi][0][hl] += acc[mi][nt][0] * w0d + acc[mi][nt][1] * w1d;
            pd[mi][1][hl] += acc[mi][nt][2] * w0d + acc[mi][nt][3] * w1d;
        }
    }
#pragma unroll
    for (int mi = 0; mi < 2; mi++)
#pragma unroll
        for (int rh = 0; rh < 2; rh++)
#pragma unroll
            for (int hl = 0; hl < 2; hl++) {
                float s = ps[mi][rh][hl], d = pd[mi][rh][hl];
                s += __shfl_xor_sync(~0u, s, 1); s += __shfl_xor_sync(~0u, s, 2);
                d += __shfl_xor_sync(~0u, d, 1); d += __shfl_xor_sync(~0u, d, 2);
                if (tg == 0) {
                    int r = m0 + wm * 32 + mi * 16 + g + rh * 8;
                    if (r < NN) {
                        int head = (n0 >> 5) + wn * 2 + hl;
                        g_as1[r * HEADS + head] = s;
                        g_ad1[r * HEADS + head] = d;
                    }
                }
            }
}

// ---------------- layer1 gather: warp per node (bf16 in, bf16 out) ----------
__global__ __launch_bounds__(256) void gather1(const float* __restrict__ b1) {
    int gw = (blockIdx.x * blockDim.x + threadIdx.x) >> 5;
    int l = threadIdx.x & 31;
    int ws = threadIdx.x >> 5;
    __shared__ float sad[8][8];
    __shared__ float sex[8][32 * 9];   // stride 9 -> conflict-free
    if (gw >= NN) return;
    int d = gw;
    int start = g_off[d];
    int deg = g_off[d + 1] - start;

    if (l < HEADS) sad[ws][l] = g_ad1[d * HEADS + l];
    __syncwarp();

    float acc[8];
#pragma unroll
    for (int j = 0; j < 8; j++) acc[j] = 0.f;
    float den = 0.f;
    int h = l >> 2;

    for (int base = 0; base < deg; base += 32) {
        int cnt = min(32, deg - base);
        int s_l = 0;
        if (l < cnt) {
            s_l = g_src[start + base + l];
            const float4* ap = reinterpret_cast<const float4*>(&g_as1[s_l * HEADS]);
            float4 v0 = ap[0];
            float4 v1 = ap[1];
            float* sx = &sex[ws][l * 9];
            sx[0] = lrelu_exp(v0.x + sad[ws][0]);
            sx[1] = lrelu_exp(v0.y + sad[ws][1]);
            sx[2] = lrelu_exp(v0.z + sad[ws][2]);
            sx[3] = lrelu_exp(v0.w + sad[ws][3]);
            sx[4] = lrelu_exp(v1.x + sad[ws][4]);
            sx[5] = lrelu_exp(v1.y + sad[ws][5]);
            sx[6] = lrelu_exp(v1.z + sad[ws][6]);
            sx[7] = lrelu_exp(v1.w + sad[ws][7]);
        }
        __syncwarp();
#pragma unroll 4
        for (int e = 0; e < cnt; e++) {
            int s = __shfl_sync(~0u, s_l, e);
            float ex = sex[ws][e * 9 + h];
            den += ex;
            uint4 rv = *reinterpret_cast<const uint4*>(&g_h1[(size_t)s * C1 + l * 8]);
            float2 f0 = __bfloat1622float2(*reinterpret_cast<__nv_bfloat162*>(&rv.x));
            float2 f1 = __bfloat1622float2(*reinterpret_cast<__nv_bfloat162*>(&rv.y));
            float2 f2 = __bfloat1622float2(*reinterpret_cast<__nv_bfloat162*>(&rv.z));
            float2 f3 = __bfloat1622float2(*reinterpret_cast<__nv_bfloat162*>(&rv.w));
            acc[0] += ex * f0.x; acc[1] += ex * f0.y;
            acc[2] += ex * f1.x; acc[3] += ex * f1.y;
            acc[4] += ex * f2.x; acc[5] += ex * f2.y;
            acc[6] += ex * f3.x; acc[7] += ex * f3.y;
        }
        __syncwarp();
    }

    float inv = 1.f / (den + 1e-16f);
    int chb = l * 8;
    float o[8];
#pragma unroll
    for (int j = 0; j < 8; j++) {
        float v = acc[j] * inv + b1[chb + j];
        o[j] = v > 0.f ? v : expm1f(v);
    }
    uint4 pk;
    pk.x = pack_bf2(o[0], o[1]);
    pk.y = pack_bf2(o[2], o[3]);
    pk.z = pack_bf2(o[4], o[5]);
    pk.w = pack_bf2(o[6], o[7]);
    *reinterpret_cast<uint4*>(&g_out1[(size_t)d * C1 + chb]) = pk;
}

// ---------------- GEMM2: h2 = out1 @ W2 (bf16 A in, bf16 out) + alpha2 ------
__global__ __launch_bounds__(256) void gemm2_kernel(const float* __restrict__ W2,
                                                    const float* __restrict__ a2s,
                                                    const float* __restrict__ a2d) {
    __shared__ float As[128][36];
    __shared__ float Bs[32][44];
    int tid = threadIdx.x;
    int lane = tid & 31, wid = tid >> 5;
    int g = lane >> 2, tg = lane & 3;
    int m0 = blockIdx.x * 128;

    float acc[5][4];
#pragma unroll
    for (int j = 0; j < 5; j++)
#pragma unroll
        for (int k = 0; k < 4; k++) acc[j][k] = 0.f;

    int a_r = tid >> 3;
    int a_c = (tid & 7) * 4;

    for (int k0 = 0; k0 < C1; k0 += 32) {
#pragma unroll
        for (int j = 0; j < 4; j++) {
            int r = a_r + 32 * j;
            int gm = m0 + r;
            float4 v = make_float4(0.f, 0.f, 0.f, 0.f);
            if (gm < NN) {
                uint2 rv = *reinterpret_cast<const uint2*>(&g_out1[(size_t)gm * C1 + k0 + a_c]);
                float2 f0 = __bfloat1622float2(*reinterpret_cast<__nv_bfloat162*>(&rv.x));
                float2 f1 = __bfloat1622float2(*reinterpret_cast<__nv_bfloat162*>(&rv.y));
                v = make_float4(f0.x, f0.y, f1.x, f1.y);
            }
            As[r][a_c + 0] = __uint_as_float(f2tf32(v.x));
            As[r][a_c + 1] = __uint_as_float(f2tf32(v.y));
            As[r][a_c + 2] = __uint_as_float(f2tf32(v.z));
            As[r][a_c + 3] = __uint_as_float(f2tf32(v.w));
        }
        for (int idx = tid; idx < 32 * OUTC; idx += 256) {
            int r = idx / OUTC, c = idx % OUTC;
            Bs[r][c] = __uint_as_float(f2tf32(W2[(size_t)(k0 + r) * OUTC + c]));
        }
        __syncthreads();
#pragma unroll
        for (int ks = 0; ks < 4; ks++) {
            int kk = ks * 8;
            unsigned a[4];
            int rb = wid * 16 + g;
            a[0] = __float_as_uint(As[rb][kk + tg]);
            a[1] = __float_as_uint(As[rb + 8][kk + tg]);
            a[2] = __float_as_uint(As[rb][kk + tg + 4]);
            a[3] = __float_as_uint(As[rb + 8][kk + tg + 4]);
#pragma unroll
            for (int nt = 0; nt < 5; nt++) {
                int col = nt * 8 + g;
                unsigned b0 = __float_as_uint(Bs[kk + tg][col]);
                unsigned b1r = __float_as_uint(Bs[kk + tg + 4][col]);
                mma_tf32(acc[nt], a, b0, b1r);
            }
        }
        __syncthreads();
    }
    int rlo = m0 + wid * 16 + g;
    int rhi = rlo + 8;
    float s_lo = 0.f, s_hi = 0.f, d_lo = 0.f, d_hi = 0.f;
#pragma unroll
    for (int nt = 0; nt < 5; nt++) {
        int c = nt * 8 + tg * 2;
        float w0s = a2s[c], w1s = a2s[c + 1];
        float w0d = a2d[c], w1d = a2d[c + 1];
        if (rlo < NN) {
            *reinterpret_cast<__nv_bfloat162*>(&g_h2[(size_t)rlo * OUTC + c]) =
                __floats2bfloat162_rn(acc[nt][0], acc[nt][1]);
        }
        if (rhi < NN) {
            *reinterpret_cast<__nv_bfloat162*>(&g_h2[(size_t)rhi * OUTC + c]) =
                __floats2bfloat162_rn(acc[nt][2], acc[nt][3]);
        }
        s_lo += acc[nt][0] * w0s + acc[nt][1] * w1s;
        s_hi += acc[nt][2] * w0s + acc[nt][3] * w1s;
        d_lo += acc[nt][0] * w0d + acc[nt][1] * w1d;
        d_hi += acc[nt][2] * w0d + acc[nt][3] * w1d;
    }
#pragma unroll
    for (int o = 1; o <= 2; o <<= 1) {
        s_lo += __shfl_xor_sync(~0u, s_lo, o);
        s_hi += __shfl_xor_sync(~0u, s_hi, o);
        d_lo += __shfl_xor_sync(~0u, d_lo, o);
        d_hi += __shfl_xor_sync(~0u, d_hi, o);
    }
    if (tg == 0) {
        if (rlo < NN) { g_as2[rlo] = s_lo; g_ad2[rlo] = d_lo; }
        if (rhi < NN) { g_as2[rhi] = s_hi; g_ad2[rhi] = d_hi; }
    }
}

// ---------------- layer2 gather: warp per node (bf16 h2), fused log_softmax --
// lanes 0..19 own channel pair (2l, 2l+1)
__global__ __launch_bounds__(256) void gather2(const float* __restrict__ b2,
                                               float* __restrict__ out) {
    int gw = (blockIdx.x * blockDim.x + threadIdx.x) >> 5;
    int l = threadIdx.x & 31;
    if (gw >= NN) return;
    int d = gw;
    int start = g_off[d];
    int deg = g_off[d + 1] - start;

    float ad = g_ad2[d];
    float accx = 0.f, accy = 0.f, denp = 0.f;

    for (int base = 0; base < deg; base += 32) {
        int cnt = min(32, deg - base);
        int s_l = 0;
        float ex_l = 0.f;
        if (l < cnt) {
            s_l = g_src[start + base + l];
            ex_l = lrelu_exp(g_as2[s_l] + ad);
        }
        denp += ex_l;
#pragma unroll 4
        for (int e = 0; e < cnt; e++) {
            int s = __shfl_sync(~0u, s_l, e);
            float ex = __shfl_sync(~0u, ex_l, e);
            if (l < OUTC / 2) {
                __nv_bfloat162 hv = *reinterpret_cast<const __nv_bfloat162*>(
                    &g_h2[(size_t)s * OUTC + 2 * l]);
                float2 f = __bfloat1622float2(hv);
                accx += ex * f.x;
                accy += ex * f.y;
            }
        }
    }
    float den = denp;
#pragma unroll
    for (int o = 16; o; o >>= 1) den += __shfl_xor_sync(~0u, den, o);
    float inv = 1.f / (den + 1e-16f);

    bool act = (l < OUTC / 2);
    float v0 = act ? (accx * inv + b2[2 * l])     : -1e30f;
    float v1 = act ? (accy * inv + b2[2 * l + 1]) : -1e30f;
    float m = fmaxf(v0, v1);
#pragma unroll
    for (int o = 16; o; o >>= 1) m = fmaxf(m, __shfl_xor_sync(~0u, m, o));
    float sum = act ? (__expf(v0 - m) + __expf(v1 - m)) : 0.f;
#pragma unroll
    for (int o = 16; o; o >>= 1) sum += __shfl_xor_sync(~0u, sum, o);
    float lse = m + logf(sum);
    if (act) {
        float2 res = make_float2(v0 - lse, v1 - lse);
        *reinterpret_cast<float2*>(&out[(size_t)d * OUTC + 2 * l]) = res;
    }
}

// ---------------- launch --------------------------------------------------------
extern "C" void kernel_launch(void* const* d_in, const int* in_sizes, int n_in,
                              void* d_out, int out_size) {
    const float* x   = (const float*)d_in[0];
    const int*   ei  = (const int*)d_in[1];
    const float* W1  = (const float*)d_in[2];
    const float* a1s = (const float*)d_in[3];
    const float* a1d = (const float*)d_in[4];
    const float* b1  = (const float*)d_in[5];
    const float* W2  = (const float*)d_in[6];
    const float* a2s = (const float*)d_in[7];
    const float* a2d = (const float*)d_in[8];
    const float* b2  = (const float*)d_in[9];
    float*       out = (float*)d_out;

    deg_hist<<<(E0 + 255) / 256, 256>>>(ei);
    scan_kernel<<<1, 1024>>>();
    fill_csr<<<(E0 + 255) / 256, 256>>>(ei);

    gemm1_kernel<<<dim3(2, (NN + 127) / 128), 256>>>(x, W1, a1s, a1d);

    gather1<<<(NN * 32 + 255) / 256, 256>>>(b1);

    gemm2_kernel<<<(NN + 127) / 128, 256>>>(W2, a2s, a2d);

    gather2<<<(NN * 32 + 255) / 256, 256>>>(b2, out);
}

// round 13
// speedup vs baseline: 1.0337x; 1.0337x over previous
#include <cuda_runtime.h>
#include <cuda_bf16.h>

#define NN   20000
#define INCH 256
#define HEADS 8
#define HID  32
#define C1   256      // HEADS*HID
#define OUTC 40
#define E0   320000
#define ET   340000   // + self loops
#define NEG  0.2f

// ---------------- scratch (device globals; no allocation allowed) ----------
__device__ __nv_bfloat16 g_h1[NN * C1];    // x @ W1 (bf16)
__device__ float g_as1[NN * HEADS];
__device__ float g_ad1[NN * HEADS];
__device__ __nv_bfloat16 g_out1[NN * C1];  // elu(aggr + b1) (bf16)
__device__ __nv_bfloat16 g_h2[NN * OUTC];  // out1 @ W2 (bf16)
__device__ float g_as2[NN];
__device__ float g_ad2[NN];
__device__ int   g_deg[NN];                // zero-init at load; re-zeroed by scan
__device__ int   g_off[NN + 1];
__device__ int   g_cur[NN];
__device__ int   g_src[ET];                // CSR payload: src node per slot

// ---------------- helpers ---------------------------------------------------
__device__ __forceinline__ unsigned f2tf32(float f) {
    unsigned r;
    asm volatile("cvt.rna.tf32.f32 %0, %1;" : "=r"(r) : "f"(f));
    return r;
}
__device__ __forceinline__ void mma_tf32(float* c, const unsigned* a, unsigned b0, unsigned b1) {
    asm volatile(
        "mma.sync.aligned.m16n8k8.row.col.f32.tf32.tf32.f32 "
        "{%0,%1,%2,%3}, {%4,%5,%6,%7}, {%8,%9}, {%0,%1,%2,%3};"
        : "+f"(c[0]), "+f"(c[1]), "+f"(c[2]), "+f"(c[3])
        : "r"(a[0]), "r"(a[1]), "r"(a[2]), "r"(a[3]), "r"(b0), "r"(b1));
}
__device__ __forceinline__ void mma_bf16(float* c, const unsigned* a, unsigned b0, unsigned b1) {
    asm volatile(
        "mma.sync.aligned.m16n8k16.row.col.f32.bf16.bf16.f32 "
        "{%0,%1,%2,%3}, {%4,%5,%6,%7}, {%8,%9}, {%0,%1,%2,%3};"
        : "+f"(c[0]), "+f"(c[1]), "+f"(c[2]), "+f"(c[3])
        : "r"(a[0]), "r"(a[1]), "r"(a[2]), "r"(a[3]), "r"(b0), "r"(b1));
}
__device__ __forceinline__ float lrelu_exp(float v) {
    v = v > 0.f ? v : NEG * v;
    return __expf(v);
}
__device__ __forceinline__ unsigned pack_bf2(float a, float b) {
    __nv_bfloat162 t = __floats2bfloat162_rn(a, b);
    return *reinterpret_cast<unsigned*>(&t);
}

// ---------------- CSR build --------------------------------------------------
__global__ void deg_hist(const int* __restrict__ ei) {
    int e = blockIdx.x * blockDim.x + threadIdx.x;
    if (e >= E0) return;
    atomicAdd(&g_deg[ei[E0 + e]], 1);
}

// single-block exclusive scan over (g_deg+1); pre-places self-loop at slot 0;
// re-zeroes g_deg so the next graph replay starts from a clean histogram.
__global__ __launch_bounds__(1024) void scan_kernel() {
    __shared__ int wsum[32];
    __shared__ int carry_s;
    int tid = threadIdx.x;
    int lane = tid & 31, wid = tid >> 5;
    if (tid == 0) carry_s = 0;
    __syncthreads();
    for (int base = 0; base < NN; base += 1024) {
        int idx = base + tid;
        int v = 0;
        if (idx < NN) {
            v = g_deg[idx] + 1;     // +1 = self-loop
            g_deg[idx] = 0;          // reset for next replay
        }
        int x = v;
#pragma unroll
        for (int o = 1; o < 32; o <<= 1) {
            int y = __shfl_up_sync(~0u, x, o);
            if (lane >= o) x += y;
        }
        if (lane == 31) wsum[wid] = x;
        __syncthreads();
        if (wid == 0) {
            int w = wsum[lane];
#pragma unroll
            for (int o = 1; o < 32; o <<= 1) {
                int y = __shfl_up_sync(~0u, w, o);
                if (lane >= o) w += y;
            }
            wsum[lane] = w;
        }
        __syncthreads();
        int incl = x + (wid ? wsum[wid - 1] : 0);
        int excl = carry_s + incl - v;
        if (idx < NN) {
            g_off[idx] = excl;
            g_cur[idx] = excl + 1;   // slot 0 taken by self-loop
            g_src[excl] = idx;       // self-loop
        }
        __syncthreads();
        if (tid == 0) carry_s += wsum[31];
        __syncthreads();
    }
    if (tid == 0) g_off[NN] = carry_s;
}

__global__ void fill_csr(const int* __restrict__ ei) {
    int e = blockIdx.x * blockDim.x + threadIdx.x;
    if (e >= E0) return;
    int s = ei[e];
    int d = ei[E0 + e];
    int pos = atomicAdd(&g_cur[d], 1);
    g_src[pos] = s;
}

// ---------------- GEMM1: h1 = x @ W1 (bf16 MMA, double-buffered) + alpha1 ---
// block 128x128, 8 warps (4m x 2n), warp tile 32x64, K-step 32 (2 x k16 MMA).
__global__ __launch_bounds__(256) void gemm1_kernel(const float* __restrict__ x,
                                                    const float* __restrict__ W1,
                                                    const float* __restrict__ a1s,
                                                    const float* __restrict__ a1d) {
    __shared__ __align__(16) __nv_bfloat16 As[2][128][40];   // [m][k]
    __shared__ __align__(16) __nv_bfloat16 Bn[2][128][40];   // [n][k] (transposed)
    int tid = threadIdx.x;
    int lane = tid & 31, wid = tid >> 5;
    int wm = wid & 3, wn = wid >> 2;
    int g = lane >> 2, tg = lane & 3;
    int m0 = blockIdx.y * 128, n0 = blockIdx.x * 128;

    float acc[2][8][4];
#pragma unroll
    for (int i = 0; i < 2; i++)
#pragma unroll
        for (int j = 0; j < 8; j++)
#pragma unroll
            for (int k = 0; k < 4; k++) acc[i][j][k] = 0.f;

    int a_r = tid >> 3;            // 0..31
    int a_c = (tid & 7) * 4;       // 0..28
    int b_k = tid >> 3;            // 0..31
    int b_n4 = tid & 7;            // 0..7

    float4 pa[4], pb[4];
    // prologue: prefetch tile 0
#pragma unroll
    for (int j = 0; j < 4; j++) {
        int gm = m0 + a_r + 32 * j;
        pa[j] = make_float4(0.f, 0.f, 0.f, 0.f);
        if (gm < NN) pa[j] = *reinterpret_cast<const float4*>(&x[(size_t)gm * INCH + a_c]);
        pb[j] = *reinterpret_cast<const float4*>(&W1[(size_t)b_k * C1 + n0 + (b_n4 + 8 * j) * 4]);
    }

    int st = 0;
#pragma unroll
    for (int t = 0; t < INCH / 32; t++) {
        // commit prefetched regs to smem[st]
#pragma unroll
        for (int j = 0; j < 4; j++) {
            int r = a_r + 32 * j;
            uint2 p;
            p.x = pack_bf2(pa[j].x, pa[j].y);
            p.y = pack_bf2(pa[j].z, pa[j].w);
            *reinterpret_cast<uint2*>(&As[st][r][a_c]) = p;
            int n = (b_n4 + 8 * j) * 4;
            Bn[st][n + 0][b_k] = __float2bfloat16(pb[j].x);
            Bn[st][n + 1][b_k] = __float2bfloat16(pb[j].y);
            Bn[st][n + 2][b_k] = __float2bfloat16(pb[j].z);
            Bn[st][n + 3][b_k] = __float2bfloat16(pb[j].w);
        }
        __syncthreads();
        // prefetch next tile (other stage -> no second sync needed)
        if (t + 1 < INCH / 32) {
            int kn = (t + 1) * 32;
#pragma unroll
            for (int j = 0; j < 4; j++) {
                int gm = m0 + a_r + 32 * j;
                pa[j] = make_float4(0.f, 0.f, 0.f, 0.f);
                if (gm < NN) pa[j] = *reinterpret_cast<const float4*>(&x[(size_t)gm * INCH + kn + a_c]);
                pb[j] = *reinterpret_cast<const float4*>(&W1[(size_t)(kn + b_k) * C1 + n0 + (b_n4 + 8 * j) * 4]);
            }
        }
        // MMAs on smem[st]: 2 k16 steps
#pragma unroll
        for (int ks = 0; ks < 2; ks++) {
            int kk = ks * 16;
            unsigned a[2][4];
#pragma unroll
            for (int mi = 0; mi < 2; mi++) {
                int rb = wm * 32 + mi * 16 + g;
                a[mi][0] = *reinterpret_cast<const unsigned*>(&As[st][rb][kk + 2 * tg]);
                a[mi][1] = *reinterpret_cast<const unsigned*>(&As[st][rb + 8][kk + 2 * tg]);
                a[mi][2] = *reinterpret_cast<const unsigned*>(&As[st][rb][kk + 2 * tg + 8]);
                a[mi][3] = *reinterpret_cast<const unsigned*>(&As[st][rb + 8][kk + 2 * tg + 8]);
            }
#pragma unroll
            for (int nt = 0; nt < 8; nt++) {
                int col = wn * 64 + nt * 8 + g;
                unsigned b0 = *reinterpret_cast<const unsigned*>(&Bn[st][col][kk + 2 * tg]);
                unsigned b1 = *reinterpret_cast<const unsigned*>(&Bn[st][col][kk + 2 * tg + 8]);
                mma_bf16(acc[0][nt], a[0], b0, b1);
                mma_bf16(acc[1][nt], a[1], b0, b1);
            }
        }
        st ^= 1;
    }

    // epilogue: store h1 (bf16) + fused alpha1 partials (fp32)
    float ps[2][2][2] = {}, pd[2][2][2] = {};
#pragma unroll
    for (int mi = 0; mi < 2; mi++) {
        int r = m0 + wm * 32 + mi * 16 + g;
#pragma unroll
        for (int nt = 0; nt < 8; nt++) {
            int c = n0 + wn * 64 + nt * 8 + tg * 2;
            int hl = nt >> 2;
            float w0s = a1s[c], w1s = a1s[c + 1];
            float w0d = a1d[c], w1d = a1d[c + 1];
            if (r < NN) {
                *reinterpret_cast<__nv_bfloat162*>(&g_h1[(size_t)r * C1 + c]) =
                    __floats2bfloat162_rn(acc[mi][nt][0], acc[mi][nt][1]);
            }
            if (r + 8 < NN) {
                *reinterpret_cast<__nv_bfloat162*>(&g_h1[(size_t)(r + 8) * C1 + c]) =
                    __floats2bfloat162_rn(acc[mi][nt][2], acc[mi][nt][3]);
            }
            ps[mi][0][hl] += acc[mi][nt][0] * w0s + acc[mi][nt][1] * w1s;
            ps[mi][1][hl] += acc[mi][nt][2] * w0s + acc[mi][nt][3] * w1s;
            pd[mi][0][hl] += acc[mi][nt][0] * w0d + acc[mi][nt][1] * w1d;
            pd[mi][1][hl] += acc[mi][nt][2] * w0d + acc[mi][nt][3] * w1d;
        }
    }
#pragma unroll
    for (int mi = 0; mi < 2; mi++)
#pragma unroll
        for (int rh = 0; rh < 2; rh++)
#pragma unroll
            for (int hl = 0; hl < 2; hl++) {
                float s = ps[mi][rh][hl], d = pd[mi][rh][hl];
                s += __shfl_xor_sync(~0u, s, 1); s += __shfl_xor_sync(~0u, s, 2);
                d += __shfl_xor_sync(~0u, d, 1); d += __shfl_xor_sync(~0u, d, 2);
                if (tg == 0) {
                    int r = m0 + wm * 32 + mi * 16 + g + rh * 8;
                    if (r < NN) {
                        int head = (n0 >> 5) + wn * 2 + hl;
                        g_as1[r * HEADS + head] = s;
                        g_ad1[r * HEADS + head] = d;
                    }
                }
            }
}

// ---------------- layer1 gather: warp per node (bf16 in, bf16 out) ----------
__global__ __launch_bounds__(256) void gather1(const float* __restrict__ b1) {
    int gw = (blockIdx.x * blockDim.x + threadIdx.x) >> 5;
    int l = threadIdx.x & 31;
    int ws = threadIdx.x >> 5;
    __shared__ float sad[8][8];
    __shared__ float sex[8][32 * 9];   // stride 9 -> conflict-free
    if (gw >= NN) return;
    int d = gw;
    int start = g_off[d];
    int deg = g_off[d + 1] - start;

    if (l < HEADS) sad[ws][l] = g_ad1[d * HEADS + l];
    __syncwarp();

    float acc[8];
#pragma unroll
    for (int j = 0; j < 8; j++) acc[j] = 0.f;
    float den = 0.f;
    int h = l >> 2;

    for (int base = 0; base < deg; base += 32) {
        int cnt = min(32, deg - base);
        int s_l = 0;
        if (l < cnt) {
            s_l = g_src[start + base + l];
            const float4* ap = reinterpret_cast<const float4*>(&g_as1[s_l * HEADS]);
            float4 v0 = ap[0];
            float4 v1 = ap[1];
            float* sx = &sex[ws][l * 9];
            sx[0] = lrelu_exp(v0.x + sad[ws][0]);
            sx[1] = lrelu_exp(v0.y + sad[ws][1]);
            sx[2] = lrelu_exp(v0.z + sad[ws][2]);
            sx[3] = lrelu_exp(v0.w + sad[ws][3]);
            sx[4] = lrelu_exp(v1.x + sad[ws][4]);
            sx[5] = lrelu_exp(v1.y + sad[ws][5]);
            sx[6] = lrelu_exp(v1.z + sad[ws][6]);
            sx[7] = lrelu_exp(v1.w + sad[ws][7]);
        }
        __syncwarp();
#pragma unroll 4
        for (int e = 0; e < cnt; e++) {
            int s = __shfl_sync(~0u, s_l, e);
            float ex = sex[ws][e * 9 + h];
            den += ex;
            uint4 rv = *reinterpret_cast<const uint4*>(&g_h1[(size_t)s * C1 + l * 8]);
            float2 f0 = __bfloat1622float2(*reinterpret_cast<__nv_bfloat162*>(&rv.x));
            float2 f1 = __bfloat1622float2(*reinterpret_cast<__nv_bfloat162*>(&rv.y));
            float2 f2 = __bfloat1622float2(*reinterpret_cast<__nv_bfloat162*>(&rv.z));
            float2 f3 = __bfloat1622float2(*reinterpret_cast<__nv_bfloat162*>(&rv.w));
            acc[0] += ex * f0.x; acc[1] += ex * f0.y;
            acc[2] += ex * f1.x; acc[3] += ex * f1.y;
            acc[4] += ex * f2.x; acc[5] += ex * f2.y;
            acc[6] += ex * f3.x; acc[7] += ex * f3.y;
        }
        __syncwarp();
    }

    float inv = 1.f / (den + 1e-16f);
    int chb = l * 8;
    float o[8];
#pragma unroll
    for (int j = 0; j < 8; j++) {
        float v = acc[j] * inv + b1[chb + j];
        o[j] = v > 0.f ? v : expm1f(v);
    }
    uint4 pk;
    pk.x = pack_bf2(o[0], o[1]);
    pk.y = pack_bf2(o[2], o[3]);
    pk.z = pack_bf2(o[4], o[5]);
    pk.w = pack_bf2(o[6], o[7]);
    *reinterpret_cast<uint4*>(&g_out1[(size_t)d * C1 + chb]) = pk;
}

// ---------------- GEMM2: h2 = out1 @ W2 (tf32, bf16 A in/out) + alpha2 ------
__global__ __launch_bounds__(256) void gemm2_kernel(const float* __restrict__ W2,
                                                    const float* __restrict__ a2s,
                                                    const float* __restrict__ a2d) {
    __shared__ float As[128][36];
    __shared__ float Bs[32][44];
    int tid = threadIdx.x;
    int lane = tid & 31, wid = tid >> 5;
    int g = lane >> 2, tg = lane & 3;
    int m0 = blockIdx.x * 128;

    float acc[5][4];
#pragma unroll
    for (int j = 0; j < 5; j++)
#pragma unroll
        for (int k = 0; k < 4; k++) acc[j][k] = 0.f;

    int a_r = tid >> 3;
    int a_c = (tid & 7) * 4;

    for (int k0 = 0; k0 < C1; k0 += 32) {
#pragma unroll
        for (int j = 0; j < 4; j++) {
            int r = a_r + 32 * j;
            int gm = m0 + r;
            float4 v = make_float4(0.f, 0.f, 0.f, 0.f);
            if (gm < NN) {
                uint2 rv = *reinterpret_cast<const uint2*>(&g_out1[(size_t)gm * C1 + k0 + a_c]);
                float2 f0 = __bfloat1622float2(*reinterpret_cast<__nv_bfloat162*>(&rv.x));
                float2 f1 = __bfloat1622float2(*reinterpret_cast<__nv_bfloat162*>(&rv.y));
                v = make_float4(f0.x, f0.y, f1.x, f1.y);
            }
            As[r][a_c + 0] = __uint_as_float(f2tf32(v.x));
            As[r][a_c + 1] = __uint_as_float(f2tf32(v.y));
            As[r][a_c + 2] = __uint_as_float(f2tf32(v.z));
            As[r][a_c + 3] = __uint_as_float(f2tf32(v.w));
        }
        for (int idx = tid; idx < 32 * OUTC; idx += 256) {
            int r = idx / OUTC, c = idx % OUTC;
            Bs[r][c] = __uint_as_float(f2tf32(W2[(size_t)(k0 + r) * OUTC + c]));
        }
        __syncthreads();
#pragma unroll
        for (int ks = 0; ks < 4; ks++) {
            int kk = ks * 8;
            unsigned a[4];
            int rb = wid * 16 + g;
            a[0] = __float_as_uint(As[rb][kk + tg]);
            a[1] = __float_as_uint(As[rb + 8][kk + tg]);
            a[2] = __float_as_uint(As[rb][kk + tg + 4]);
            a[3] = __float_as_uint(As[rb + 8][kk + tg + 4]);
#pragma unroll
            for (int nt = 0; nt < 5; nt++) {
                int col = nt * 8 + g;
                unsigned b0 = __float_as_uint(Bs[kk + tg][col]);
                unsigned b1r = __float_as_uint(Bs[kk + tg + 4][col]);
                mma_tf32(acc[nt], a, b0, b1r);
            }
        }
        __syncthreads();
    }
    int rlo = m0 + wid * 16 + g;
    int rhi = rlo + 8;
    float s_lo = 0.f, s_hi = 0.f, d_lo = 0.f, d_hi = 0.f;
#pragma unroll
    for (int nt = 0; nt < 5; nt++) {
        int c = nt * 8 + tg * 2;
        float w0s = a2s[c], w1s = a2s[c + 1];
        float w0d = a2d[c], w1d = a2d[c + 1];
        if (rlo < NN) {
            *reinterpret_cast<__nv_bfloat162*>(&g_h2[(size_t)rlo * OUTC + c]) =
                __floats2bfloat162_rn(acc[nt][0], acc[nt][1]);
        }
        if (rhi < NN) {
            *reinterpret_cast<__nv_bfloat162*>(&g_h2[(size_t)rhi * OUTC + c]) =
                __floats2bfloat162_rn(acc[nt][2], acc[nt][3]);
        }
        s_lo += acc[nt][0] * w0s + acc[nt][1] * w1s;
        s_hi += acc[nt][2] * w0s + acc[nt][3] * w1s;
        d_lo += acc[nt][0] * w0d + acc[nt][1] * w1d;
        d_hi += acc[nt][2] * w0d + acc[nt][3] * w1d;
    }
#pragma unroll
    for (int o = 1; o <= 2; o <<= 1) {
        s_lo += __shfl_xor_sync(~0u, s_lo, o);
        s_hi += __shfl_xor_sync(~0u, s_hi, o);
        d_lo += __shfl_xor_sync(~0u, d_lo, o);
        d_hi += __shfl_xor_sync(~0u, d_hi, o);
    }
    if (tg == 0) {
        if (rlo < NN) { g_as2[rlo] = s_lo; g_ad2[rlo] = d_lo; }
        if (rhi < NN) { g_as2[rhi] = s_hi; g_ad2[rhi] = d_hi; }
    }
}

// ---------------- layer2 gather: warp per node (bf16 h2), fused log_softmax --
__global__ __launch_bounds__(256) void gather2(const float* __restrict__ b2,
                                               float* __restrict__ out) {
    int gw = (blockIdx.x * blockDim.x + threadIdx.x) >> 5;
    int l = threadIdx.x & 31;
    if (gw >= NN) return;
    int d = gw;
    int start = g_off[d];
    int deg = g_off[d + 1] - start;

    float ad = g_ad2[d];
    float accx = 0.f, accy = 0.f, denp = 0.f;

    for (int base = 0; base < deg; base += 32) {
        int cnt = min(32, deg - base);
        int s_l = 0;
        float ex_l = 0.f;
        if (l < cnt) {
            s_l = g_src[start + base + l];
            ex_l = lrelu_exp(g_as2[s_l] + ad);
        }
        denp += ex_l;
#pragma unroll 4
        for (int e = 0; e < cnt; e++) {
            int s = __shfl_sync(~0u, s_l, e);
            float ex = __shfl_sync(~0u, ex_l, e);
            if (l < OUTC / 2) {
                __nv_bfloat162 hv = *reinterpret_cast<const __nv_bfloat162*>(
                    &g_h2[(size_t)s * OUTC + 2 * l]);
                float2 f = __bfloat1622float2(hv);
                accx += ex * f.x;
                accy += ex * f.y;
            }
        }
    }
    float den = denp;
#pragma unroll
    for (int o = 16; o; o >>= 1) den += __shfl_xor_sync(~0u, den, o);
    float inv = 1.f / (den + 1e-16f);

    bool act = (l < OUTC / 2);
    float v0 = act ? (accx * inv + b2[2 * l])     : -1e30f;
    float v1 = act ? (accy * inv + b2[2 * l + 1]) : -1e30f;
    float m = fmaxf(v0, v1);
#pragma unroll
    for (int o = 16; o; o >>= 1) m = fmaxf(m, __shfl_xor_sync(~0u, m, o));
    float sum = act ? (__expf(v0 - m) + __expf(v1 - m)) : 0.f;
#pragma unroll
    for (int o = 16; o; o >>= 1) sum += __shfl_xor_sync(~0u, sum, o);
    float lse = m + logf(sum);
    if (act) {
        float2 res = make_float2(v0 - lse, v1 - lse);
        *reinterpret_cast<float2*>(&out[(size_t)d * OUTC + 2 * l]) = res;
    }
}

// ---------------- launch --------------------------------------------------------
extern "C" void kernel_launch(void* const* d_in, const int* in_sizes, int n_in,
                              void* d_out, int out_size) {
    const float* x   = (const float*)d_in[0];
    const int*   ei  = (const int*)d_in[1];
    const float* W1  = (const float*)d_in[2];
    const float* a1s = (const float*)d_in[3];
    const float* a1d = (const float*)d_in[4];
    const float* b1  = (const float*)d_in[5];
    const float* W2  = (const float*)d_in[6];
    const float* a2s = (const float*)d_in[7];
    const float* a2d = (const float*)d_in[8];
    const float* b2  = (const float*)d_in[9];
    float*       out = (float*)d_out;

    deg_hist<<<(E0 + 255) / 256, 256>>>(ei);
    scan_kernel<<<1, 1024>>>();
    fill_csr<<<(E0 + 255) / 256, 256>>>(ei);

    gemm1_kernel<<<dim3(2, (NN + 127) / 128), 256>>>(x, W1, a1s, a1d);

    gather1<<<(NN * 32 + 255) / 256, 256>>>(b1);

    gemm2_kernel<<<(NN + 127) / 128, 256>>>(W2, a2s, a2d);

    gather2<<<(NN * 32 + 255) / 256, 256>>>(b2, out);
}

// round 14
// speedup vs baseline: 1.0592x; 1.0246x over previous
#include <cuda_runtime.h>
#include <cuda_bf16.h>

#define NN   20000
#define INCH 256
#define HEADS 8
#define HID  32
#define C1   256      // HEADS*HID
#define OUTC 40
#define E0   320000
#define ET   340000   // + self loops
#define NEG  0.2f

// ---------------- scratch (device globals; no allocation allowed) ----------
__device__ __nv_bfloat16 g_h1[NN * C1];    // x @ W1 (bf16)
__device__ float g_as1[NN * HEADS];
__device__ float g_ad1[NN * HEADS];
__device__ __nv_bfloat16 g_out1[NN * C1];  // elu(aggr + b1) (bf16)
__device__ __nv_bfloat16 g_h2[NN * OUTC];  // out1 @ W2 (bf16)
__device__ float g_as2[NN];
__device__ float g_ad2[NN];
__device__ int   g_deg[NN];                // zero-init at load; re-zeroed by scan
__device__ int   g_off[NN + 1];
__device__ int   g_cur[NN];
__device__ int   g_src[ET];                // CSR payload: src node per slot

// ---------------- helpers ---------------------------------------------------
__device__ __forceinline__ unsigned f2tf32(float f) {
    unsigned r;
    asm volatile("cvt.rna.tf32.f32 %0, %1;" : "=r"(r) : "f"(f));
    return r;
}
__device__ __forceinline__ void mma_tf32(float* c, const unsigned* a, unsigned b0, unsigned b1) {
    asm volatile(
        "mma.sync.aligned.m16n8k8.row.col.f32.tf32.tf32.f32 "
        "{%0,%1,%2,%3}, {%4,%5,%6,%7}, {%8,%9}, {%0,%1,%2,%3};"
        : "+f"(c[0]), "+f"(c[1]), "+f"(c[2]), "+f"(c[3])
        : "r"(a[0]), "r"(a[1]), "r"(a[2]), "r"(a[3]), "r"(b0), "r"(b1));
}
__device__ __forceinline__ float lrelu_exp(float v) {
    v = v > 0.f ? v : NEG * v;
    return __expf(v);
}
__device__ __forceinline__ unsigned pack_bf2(float a, float b) {
    __nv_bfloat162 t = __floats2bfloat162_rn(a, b);
    return *reinterpret_cast<unsigned*>(&t);
}
__device__ __forceinline__ void cp16(unsigned dst, const void* src, int nbytes) {
    asm volatile("cp.async.cg.shared.global [%0], [%1], 16, %2;"
                 :: "r"(dst), "l"(src), "r"(nbytes) : "memory");
}

// ---------------- CSR build --------------------------------------------------
__global__ void deg_hist(const int* __restrict__ ei) {
    int e = blockIdx.x * blockDim.x + threadIdx.x;
    if (e >= E0) return;
    atomicAdd(&g_deg[ei[E0 + e]], 1);
}

__global__ __launch_bounds__(1024) void scan_kernel() {
    __shared__ int wsum[32];
    __shared__ int carry_s;
    int tid = threadIdx.x;
    int lane = tid & 31, wid = tid >> 5;
    if (tid == 0) carry_s = 0;
    __syncthreads();
    for (int base = 0; base < NN; base += 1024) {
        int idx = base + tid;
        int v = 0;
        if (idx < NN) {
            v = g_deg[idx] + 1;     // +1 = self-loop
            g_deg[idx] = 0;          // reset for next replay
        }
        int x = v;
#pragma unroll
        for (int o = 1; o < 32; o <<= 1) {
            int y = __shfl_up_sync(~0u, x, o);
            if (lane >= o) x += y;
        }
        if (lane == 31) wsum[wid] = x;
        __syncthreads();
        if (wid == 0) {
            int w = wsum[lane];
#pragma unroll
            for (int o = 1; o < 32; o <<= 1) {
                int y = __shfl_up_sync(~0u, w, o);
                if (lane >= o) w += y;
            }
            wsum[lane] = w;
        }
        __syncthreads();
        int incl = x + (wid ? wsum[wid - 1] : 0);
        int excl = carry_s + incl - v;
        if (idx < NN) {
            g_off[idx] = excl;
            g_cur[idx] = excl + 1;
            g_src[excl] = idx;       // self-loop at slot 0
        }
        __syncthreads();
        if (tid == 0) carry_s += wsum[31];
        __syncthreads();
    }
    if (tid == 0) g_off[NN] = carry_s;
}

__global__ void fill_csr(const int* __restrict__ ei) {
    int e = blockIdx.x * blockDim.x + threadIdx.x;
    if (e >= E0) return;
    int s = ei[e];
    int d = ei[E0 + e];
    int pos = atomicAdd(&g_cur[d], 1);
    g_src[pos] = s;
}

// ---------------- GEMM1: h1 = x @ W1 (tf32, cp.async 2-stage) + alpha1 ------
// block tile 64x128, BK=16, 8 warps (2m x 4n), warp tile 32x32.
// tf32 MMAs fed with raw fp32 bits (HW truncation).
__global__ __launch_bounds__(256, 3) void gemm1_kernel(const float* __restrict__ x,
                                                       const float* __restrict__ W1,
                                                       const float* __restrict__ a1s,
                                                       const float* __restrict__ a1d) {
    __shared__ __align__(16) float As[2][64][20];    // [m][k], stride 20 conflict-free
    __shared__ __align__(16) float Bs[2][16][136];   // [k][n], stride 136 conflict-free
    int tid = threadIdx.x;
    int lane = tid & 31, wid = tid >> 5;
    int wm = wid & 1, wn = wid >> 1;      // 2 m-warps x 4 n-warps
    int g = lane >> 2, tg = lane & 3;
    int m0 = blockIdx.y * 64, n0 = blockIdx.x * 128;

    float acc[2][4][4];
#pragma unroll
    for (int i = 0; i < 2; i++)
#pragma unroll
        for (int j = 0; j < 4; j++)
#pragma unroll
            for (int k = 0; k < 4; k++) acc[i][j][k] = 0.f;

    // cp.async chunk coordinates
    int a_row = tid >> 2;            // 0..63
    int a_off = (tid & 3) * 4;       // float offset {0,4,8,12}
    int a_gm  = m0 + a_row;
    const float* a_src_base = &x[(size_t)min(a_gm, NN - 1) * INCH + a_off];
    int a_bytes = (a_gm < NN) ? 16 : 0;

#define GEMM1_ISSUE(t, st)                                                          \
    {                                                                               \
        int k0_ = (t) * 16;                                                         \
        cp16((unsigned)__cvta_generic_to_shared(&As[st][a_row][a_off]),             \
             a_src_base + k0_, a_bytes);                                            \
        _Pragma("unroll")                                                           \
        for (int j_ = 0; j_ < 2; j_++) {                                            \
            int c_ = tid + j_ * 256;                                                \
            int kr_ = c_ >> 5, ob_ = (c_ & 31) * 4;                                 \
            cp16((unsigned)__cvta_generic_to_shared(&Bs[st][kr_][ob_]),             \
                 &W1[(size_t)(k0_ + kr_) * C1 + n0 + ob_], 16);                     \
        }                                                                           \
        asm volatile("cp.async.commit_group;" ::: "memory");                        \
    }

    GEMM1_ISSUE(0, 0);

#pragma unroll
    for (int t = 0; t < 16; t++) {
        int st = t & 1;
        if (t < 15) { GEMM1_ISSUE(t + 1, st ^ 1); }
        if (t < 15) asm volatile("cp.async.wait_group 1;" ::: "memory");
        else        asm volatile("cp.async.wait_group 0;" ::: "memory");
        __syncthreads();
#pragma unroll
        for (int ks = 0; ks < 2; ks++) {
            int kk = ks * 8;
            unsigned a[2][4];
#pragma unroll
            for (int mi = 0; mi < 2; mi++) {
                int rb = wm * 32 + mi * 16 + g;
                a[mi][0] = __float_as_uint(As[st][rb][kk + tg]);
                a[mi][1] = __float_as_uint(As[st][rb + 8][kk + tg]);
                a[mi][2] = __float_as_uint(As[st][rb][kk + tg + 4]);
                a[mi][3] = __float_as_uint(As[st][rb + 8][kk + tg + 4]);
            }
#pragma unroll
            for (int nt = 0; nt < 4; nt++) {
                int col = wn * 32 + nt * 8 + g;
                unsigned b0 = __float_as_uint(Bs[st][kk + tg][col]);
                unsigned b1 = __float_as_uint(Bs[st][kk + tg + 4][col]);
                mma_tf32(acc[0][nt], a[0], b0, b1);
                mma_tf32(acc[1][nt], a[1], b0, b1);
            }
        }
        __syncthreads();
    }
#undef GEMM1_ISSUE

    // epilogue: store h1 (bf16) + fused alpha1 (each warp = exactly 1 head)
    int head = (n0 >> 5) + wn;
    float ps[2][2] = {}, pd[2][2] = {};
#pragma unroll
    for (int mi = 0; mi < 2; mi++) {
        int r = m0 + wm * 32 + mi * 16 + g;
#pragma unroll
        for (int nt = 0; nt < 4; nt++) {
            int c = n0 + wn * 32 + nt * 8 + tg * 2;
            float w0s = a1s[c], w1s = a1s[c + 1];
            float w0d = a1d[c], w1d = a1d[c + 1];
            if (r < NN) {
                *reinterpret_cast<__nv_bfloat162*>(&g_h1[(size_t)r * C1 + c]) =
                    __floats2bfloat162_rn(acc[mi][nt][0], acc[mi][nt][1]);
            }
            if (r + 8 < NN) {
                *reinterpret_cast<__nv_bfloat162*>(&g_h1[(size_t)(r + 8) * C1 + c]) =
                    __floats2bfloat162_rn(acc[mi][nt][2], acc[mi][nt][3]);
            }
            ps[mi][0] += acc[mi][nt][0] * w0s + acc[mi][nt][1] * w1s;
            ps[mi][1] += acc[mi][nt][2] * w0s + acc[mi][nt][3] * w1s;
            pd[mi][0] += acc[mi][nt][0] * w0d + acc[mi][nt][1] * w1d;
            pd[mi][1] += acc[mi][nt][2] * w0d + acc[mi][nt][3] * w1d;
        }
    }
#pragma unroll
    for (int mi = 0; mi < 2; mi++)
#pragma unroll
        for (int rh = 0; rh < 2; rh++) {
            float s = ps[mi][rh], d = pd[mi][rh];
            s += __shfl_xor_sync(~0u, s, 1); s += __shfl_xor_sync(~0u, s, 2);
            d += __shfl_xor_sync(~0u, d, 1); d += __shfl_xor_sync(~0u, d, 2);
            if (tg == 0) {
                int r = m0 + wm * 32 + mi * 16 + g + rh * 8;
                if (r < NN) {
                    g_as1[r * HEADS + head] = s;
                    g_ad1[r * HEADS + head] = d;
                }
            }
        }
}

// ---------------- layer1 gather: warp per node (bf16 in, bf16 out) ----------
__global__ __launch_bounds__(256) void gather1(const float* __restrict__ b1) {
    int gw = (blockIdx.x * blockDim.x + threadIdx.x) >> 5;
    int l = threadIdx.x & 31;
    int ws = threadIdx.x >> 5;
    __shared__ float sad[8][8];
    __shared__ float sex[8][32 * 9];   // stride 9 -> conflict-free
    if (gw >= NN) return;
    int d = gw;
    int start = g_off[d];
    int deg = g_off[d + 1] - start;

    if (l < HEADS) sad[ws][l] = g_ad1[d * HEADS + l];
    __syncwarp();

    float acc[8];
#pragma unroll
    for (int j = 0; j < 8; j++) acc[j] = 0.f;
    float den = 0.f;
    int h = l >> 2;

    for (int base = 0; base < deg; base += 32) {
        int cnt = min(32, deg - base);
        int s_l = 0;
        if (l < cnt) {
            s_l = g_src[start + base + l];
            const float4* ap = reinterpret_cast<const float4*>(&g_as1[s_l * HEADS]);
            float4 v0 = ap[0];
            float4 v1 = ap[1];
            float* sx = &sex[ws][l * 9];
            sx[0] = lrelu_exp(v0.x + sad[ws][0]);
            sx[1] = lrelu_exp(v0.y + sad[ws][1]);
            sx[2] = lrelu_exp(v0.z + sad[ws][2]);
            sx[3] = lrelu_exp(v0.w + sad[ws][3]);
            sx[4] = lrelu_exp(v1.x + sad[ws][4]);
            sx[5] = lrelu_exp(v1.y + sad[ws][5]);
            sx[6] = lrelu_exp(v1.z + sad[ws][6]);
            sx[7] = lrelu_exp(v1.w + sad[ws][7]);
        }
        __syncwarp();
#pragma unroll 4
        for (int e = 0; e < cnt; e++) {
            int s = __shfl_sync(~0u, s_l, e);
            float ex = sex[ws][e * 9 + h];
            den += ex;
            uint4 rv = *reinterpret_cast<const uint4*>(&g_h1[(size_t)s * C1 + l * 8]);
            float2 f0 = __bfloat1622float2(*reinterpret_cast<__nv_bfloat162*>(&rv.x));
            float2 f1 = __bfloat1622float2(*reinterpret_cast<__nv_bfloat162*>(&rv.y));
            float2 f2 = __bfloat1622float2(*reinterpret_cast<__nv_bfloat162*>(&rv.z));
            float2 f3 = __bfloat1622float2(*reinterpret_cast<__nv_bfloat162*>(&rv.w));
            acc[0] += ex * f0.x; acc[1] += ex * f0.y;
            acc[2] += ex * f1.x; acc[3] += ex * f1.y;
            acc[4] += ex * f2.x; acc[5] += ex * f2.y;
            acc[6] += ex * f3.x; acc[7] += ex * f3.y;
        }
        __syncwarp();
    }

    float inv = 1.f / (den + 1e-16f);
    int chb = l * 8;
    float o[8];
#pragma unroll
    for (int j = 0; j < 8; j++) {
        float v = acc[j] * inv + b1[chb + j];
        o[j] = v > 0.f ? v : expm1f(v);
    }
    uint4 pk;
    pk.x = pack_bf2(o[0], o[1]);
    pk.y = pack_bf2(o[2], o[3]);
    pk.z = pack_bf2(o[4], o[5]);
    pk.w = pack_bf2(o[6], o[7]);
    *reinterpret_cast<uint4*>(&g_out1[(size_t)d * C1 + chb]) = pk;
}

// ---------------- GEMM2: h2 = out1 @ W2 (tf32, bf16 A in/out) + alpha2 ------
__global__ __launch_bounds__(256) void gemm2_kernel(const float* __restrict__ W2,
                                                    const float* __restrict__ a2s,
                                                    const float* __restrict__ a2d) {
    __shared__ float As[128][36];
    __shared__ float Bs[32][44];
    int tid = threadIdx.x;
    int lane = tid & 31, wid = tid >> 5;
    int g = lane >> 2, tg = lane & 3;
    int m0 = blockIdx.x * 128;

    float acc[5][4];
#pragma unroll
    for (int j = 0; j < 5; j++)
#pragma unroll
        for (int k = 0; k < 4; k++) acc[j][k] = 0.f;

    int a_r = tid >> 3;
    int a_c = (tid & 7) * 4;

    for (int k0 = 0; k0 < C1; k0 += 32) {
#pragma unroll
        for (int j = 0; j < 4; j++) {
            int r = a_r + 32 * j;
            int gm = m0 + r;
            float4 v = make_float4(0.f, 0.f, 0.f, 0.f);
            if (gm < NN) {
                uint2 rv = *reinterpret_cast<const uint2*>(&g_out1[(size_t)gm * C1 + k0 + a_c]);
                float2 f0 = __bfloat1622float2(*reinterpret_cast<__nv_bfloat162*>(&rv.x));
                float2 f1 = __bfloat1622float2(*reinterpret_cast<__nv_bfloat162*>(&rv.y));
                v = make_float4(f0.x, f0.y, f1.x, f1.y);
            }
            As[r][a_c + 0] = v.x;
            As[r][a_c + 1] = v.y;
            As[r][a_c + 2] = v.z;
            As[r][a_c + 3] = v.w;
        }
        for (int idx = tid; idx < 32 * OUTC; idx += 256) {
            int r = idx / OUTC, c = idx % OUTC;
            Bs[r][c] = __uint_as_float(f2tf32(W2[(size_t)(k0 + r) * OUTC + c]));
        }
        __syncthreads();
#pragma unroll
        for (int ks = 0; ks < 4; ks++) {
            int kk = ks * 8;
            unsigned a[4];
            int rb = wid * 16 + g;
            a[0] = __float_as_uint(As[rb][kk + tg]);
            a[1] = __float_as_uint(As[rb + 8][kk + tg]);
            a[2] = __float_as_uint(As[rb][kk + tg + 4]);
            a[3] = __float_as_uint(As[rb + 8][kk + tg + 4]);
#pragma unroll
            for (int nt = 0; nt < 5; nt++) {
                int col = nt * 8 + g;
                unsigned b0 = __float_as_uint(Bs[kk + tg][col]);
                unsigned b1r = __float_as_uint(Bs[kk + tg + 4][col]);
                mma_tf32(acc[nt], a, b0, b1r);
            }
        }
        __syncthreads();
    }
    int rlo = m0 + wid * 16 + g;
    int rhi = rlo + 8;
    float s_lo = 0.f, s_hi = 0.f, d_lo = 0.f, d_hi = 0.f;
#pragma unroll
    for (int nt = 0; nt < 5; nt++) {
        int c = nt * 8 + tg * 2;
        float w0s = a2s[c], w1s = a2s[c + 1];
        float w0d = a2d[c], w1d = a2d[c + 1];
        if (rlo < NN) {
            *reinterpret_cast<__nv_bfloat162*>(&g_h2[(size_t)rlo * OUTC + c]) =
                __floats2bfloat162_rn(acc[nt][0], acc[nt][1]);
        }
        if (rhi < NN) {
            *reinterpret_cast<__nv_bfloat162*>(&g_h2[(size_t)rhi * OUTC + c]) =
                __floats2bfloat162_rn(acc[nt][2], acc[nt][3]);
        }
        s_lo += acc[nt][0] * w0s + acc[nt][1] * w1s;
        s_hi += acc[nt][2] * w0s + acc[nt][3] * w1s;
        d_lo += acc[nt][0] * w0d + acc[nt][1] * w1d;
        d_hi += acc[nt][2] * w0d + acc[nt][3] * w1d;
    }
#pragma unroll
    for (int o = 1; o <= 2; o <<= 1) {
        s_lo += __shfl_xor_sync(~0u, s_lo, o);
        s_hi += __shfl_xor_sync(~0u, s_hi, o);
        d_lo += __shfl_xor_sync(~0u, d_lo, o);
        d_hi += __shfl_xor_sync(~0u, d_hi, o);
    }
    if (tg == 0) {
        if (rlo < NN) { g_as2[rlo] = s_lo; g_ad2[rlo] = d_lo; }
        if (rhi < NN) { g_as2[rhi] = s_hi; g_ad2[rhi] = d_hi; }
    }
}

// ---------------- layer2 gather: warp per node (bf16 h2), fused log_softmax --
__global__ __launch_bounds__(256) void gather2(const float* __restrict__ b2,
                                               float* __restrict__ out) {
    int gw = (blockIdx.x * blockDim.x + threadIdx.x) >> 5;
    int l = threadIdx.x & 31;
    if (gw >= NN) return;
    int d = gw;
    int start = g_off[d];
    int deg = g_off[d + 1] - start;

    float ad = g_ad2[d];
    float accx = 0.f, accy = 0.f, denp = 0.f;

    for (int base = 0; base < deg; base += 32) {
        int cnt = min(32, deg - base);
        int s_l = 0;
        float ex_l = 0.f;
        if (l < cnt) {
            s_l = g_src[start + base + l];
            ex_l = lrelu_exp(g_as2[s_l] + ad);
        }
        denp += ex_l;
#pragma unroll 4
        for (int e = 0; e < cnt; e++) {
            int s = __shfl_sync(~0u, s_l, e);
            float ex = __shfl_sync(~0u, ex_l, e);
            if (l < OUTC / 2) {
                __nv_bfloat162 hv = *reinterpret_cast<const __nv_bfloat162*>(
                    &g_h2[(size_t)s * OUTC + 2 * l]);
                float2 f = __bfloat1622float2(hv);
                accx += ex * f.x;
                accy += ex * f.y;
            }
        }
    }
    float den = denp;
#pragma unroll
    for (int o = 16; o; o >>= 1) den += __shfl_xor_sync(~0u, den, o);
    float inv = 1.f / (den + 1e-16f);

    bool act = (l < OUTC / 2);
    float v0 = act ? (accx * inv + b2[2 * l])     : -1e30f;
    float v1 = act ? (accy * inv + b2[2 * l + 1]) : -1e30f;
    float m = fmaxf(v0, v1);
#pragma unroll
    for (int o = 16; o; o >>= 1) m = fmaxf(m, __shfl_xor_sync(~0u, m, o));
    float sum = act ? (__expf(v0 - m) + __expf(v1 - m)) : 0.f;
#pragma unroll
    for (int o = 16; o; o >>= 1) sum += __shfl_xor_sync(~0u, sum, o);
    float lse = m + logf(sum);
    if (act) {
        float2 res = make_float2(v0 - lse, v1 - lse);
        *reinterpret_cast<float2*>(&out[(size_t)d * OUTC + 2 * l]) = res;
    }
}

// ---------------- launch --------------------------------------------------------
extern "C" void kernel_launch(void* const* d_in, const int* in_sizes, int n_in,
                              void* d_out, int out_size) {
    const float* x   = (const float*)d_in[0];
    const int*   ei  = (const int*)d_in[1];
    const float* W1  = (const float*)d_in[2];
    const float* a1s = (const float*)d_in[3];
    const float* a1d = (const float*)d_in[4];
    const float* b1  = (const float*)d_in[5];
    const float* W2  = (const float*)d_in[6];
    const float* a2s = (const float*)d_in[7];
    const float* a2d = (const float*)d_in[8];
    const float* b2  = (const float*)d_in[9];
    float*       out = (float*)d_out;

    deg_hist<<<(E0 + 255) / 256, 256>>>(ei);
    scan_kernel<<<1, 1024>>>();
    fill_csr<<<(E0 + 255) / 256, 256>>>(ei);

    gemm1_kernel<<<dim3(2, (NN + 63) / 64), 256>>>(x, W1, a1s, a1d);

    gather1<<<(NN * 32 + 255) / 256, 256>>>(b1);

    gemm2_kernel<<<(NN + 127) / 128, 256>>>(W2, a2s, a2d);

    gather2<<<(NN * 32 + 255) / 256, 256>>>(b2, out);
}

// round 15
// speedup vs baseline: 1.1013x; 1.0398x over previous
#include <cuda_runtime.h>
#include <cuda_bf16.h>

#define NN   20000
#define INCH 256
#define HEADS 8
#define HID  32
#define C1   256      // HEADS*HID
#define OUTC 40
#define E0   320000
#define ET   340000   // + self loops
#define NEG  0.2f

// ---------------- scratch (device globals; no allocation allowed) ----------
__device__ __nv_bfloat16 g_h1[NN * C1];    // x @ W1 (bf16)
__device__ float g_as1[NN * HEADS];
__device__ float g_ad1[NN * HEADS];
__device__ __nv_bfloat16 g_out1[NN * C1];  // elu(aggr + b1) (bf16)
__device__ __nv_bfloat16 g_h2[NN * OUTC];  // out1 @ W2 (bf16)
__device__ float g_as2[NN];
__device__ float g_ad2[NN];
__device__ int   g_deg[NN];                // zero-init at load; re-zeroed by scan
__device__ int   g_off[NN + 1];
__device__ int   g_cur[NN];
__device__ int   g_src[ET];                // CSR payload: src node per slot

// ---------------- helpers ---------------------------------------------------
__device__ __forceinline__ unsigned f2tf32(float f) {
    unsigned r;
    asm volatile("cvt.rna.tf32.f32 %0, %1;" : "=r"(r) : "f"(f));
    return r;
}
__device__ __forceinline__ void mma_tf32(float* c, const unsigned* a, unsigned b0, unsigned b1) {
    asm volatile(
        "mma.sync.aligned.m16n8k8.row.col.f32.tf32.tf32.f32 "
        "{%0,%1,%2,%3}, {%4,%5,%6,%7}, {%8,%9}, {%0,%1,%2,%3};"
        : "+f"(c[0]), "+f"(c[1]), "+f"(c[2]), "+f"(c[3])
        : "r"(a[0]), "r"(a[1]), "r"(a[2]), "r"(a[3]), "r"(b0), "r"(b1));
}
__device__ __forceinline__ float lrelu_exp(float v) {
    v = v > 0.f ? v : NEG * v;
    return __expf(v);
}
__device__ __forceinline__ unsigned pack_bf2(float a, float b) {
    __nv_bfloat162 t = __floats2bfloat162_rn(a, b);
    return *reinterpret_cast<unsigned*>(&t);
}
__device__ __forceinline__ void cp16(unsigned dst, const void* src, int nbytes) {
    asm volatile("cp.async.cg.shared.global [%0], [%1], 16, %2;"
                 :: "r"(dst), "l"(src), "r"(nbytes) : "memory");
}

// ---------------- CSR build --------------------------------------------------
__global__ void deg_hist(const int* __restrict__ ei) {
    int e = blockIdx.x * blockDim.x + threadIdx.x;
    if (e >= E0) return;
    atomicAdd(&g_deg[ei[E0 + e]], 1);
}

__global__ __launch_bounds__(1024) void scan_kernel() {
    __shared__ int wsum[32];
    __shared__ int carry_s;
    int tid = threadIdx.x;
    int lane = tid & 31, wid = tid >> 5;
    if (tid == 0) carry_s = 0;
    __syncthreads();
    for (int base = 0; base < NN; base += 1024) {
        int idx = base + tid;
        int v = 0;
        if (idx < NN) {
            v = g_deg[idx] + 1;     // +1 = self-loop
            g_deg[idx] = 0;          // reset for next replay
        }
        int x = v;
#pragma unroll
        for (int o = 1; o < 32; o <<= 1) {
            int y = __shfl_up_sync(~0u, x, o);
            if (lane >= o) x += y;
        }
        if (lane == 31) wsum[wid] = x;
        __syncthreads();
        if (wid == 0) {
            int w = wsum[lane];
#pragma unroll
            for (int o = 1; o < 32; o <<= 1) {
                int y = __shfl_up_sync(~0u, w, o);
                if (lane >= o) w += y;
            }
            wsum[lane] = w;
        }
        __syncthreads();
        int incl = x + (wid ? wsum[wid - 1] : 0);
        int excl = carry_s + incl - v;
        if (idx < NN) {
            g_off[idx] = excl;
            g_cur[idx] = excl + 1;
            g_src[excl] = idx;       // self-loop at slot 0
        }
        __syncthreads();
        if (tid == 0) carry_s += wsum[31];
        __syncthreads();
    }
    if (tid == 0) g_off[NN] = carry_s;
}

__global__ void fill_csr(const int* __restrict__ ei) {
    int e = blockIdx.x * blockDim.x + threadIdx.x;
    if (e >= E0) return;
    int s = ei[e];
    int d = ei[E0 + e];
    int pos = atomicAdd(&g_cur[d], 1);
    g_src[pos] = s;
}

// ---------------- GEMM1: h1 = x @ W1 (tf32, cp.async 2-stage) + alpha1 ------
__global__ __launch_bounds__(256, 3) void gemm1_kernel(const float* __restrict__ x,
                                                       const float* __restrict__ W1,
                                                       const float* __restrict__ a1s,
                                                       const float* __restrict__ a1d) {
    __shared__ __align__(16) float As[2][64][20];    // [m][k], stride 20 conflict-free
    __shared__ __align__(16) float Bs[2][16][136];   // [k][n], stride 136 conflict-free
    int tid = threadIdx.x;
    int lane = tid & 31, wid = tid >> 5;
    int wm = wid & 1, wn = wid >> 1;      // 2 m-warps x 4 n-warps
    int g = lane >> 2, tg = lane & 3;
    int m0 = blockIdx.y * 64, n0 = blockIdx.x * 128;

    float acc[2][4][4];
#pragma unroll
    for (int i = 0; i < 2; i++)
#pragma unroll
        for (int j = 0; j < 4; j++)
#pragma unroll
            for (int k = 0; k < 4; k++) acc[i][j][k] = 0.f;

    int a_row = tid >> 2;            // 0..63
    int a_off = (tid & 3) * 4;       // float offset {0,4,8,12}
    int a_gm  = m0 + a_row;
    const float* a_src_base = &x[(size_t)min(a_gm, NN - 1) * INCH + a_off];
    int a_bytes = (a_gm < NN) ? 16 : 0;

#define GEMM1_ISSUE(t, st)                                                          \
    {                                                                               \
        int k0_ = (t) * 16;                                                         \
        cp16((unsigned)__cvta_generic_to_shared(&As[st][a_row][a_off]),             \
             a_src_base + k0_, a_bytes);                                            \
        _Pragma("unroll")                                                           \
        for (int j_ = 0; j_ < 2; j_++) {                                            \
            int c_ = tid + j_ * 256;                                                \
            int kr_ = c_ >> 5, ob_ = (c_ & 31) * 4;                                 \
            cp16((unsigned)__cvta_generic_to_shared(&Bs[st][kr_][ob_]),             \
                 &W1[(size_t)(k0_ + kr_) * C1 + n0 + ob_], 16);                     \
        }                                                                           \
        asm volatile("cp.async.commit_group;" ::: "memory");                        \
    }

    GEMM1_ISSUE(0, 0);

#pragma unroll
    for (int t = 0; t < 16; t++) {
        int st = t & 1;
        if (t < 15) { GEMM1_ISSUE(t + 1, st ^ 1); }
        if (t < 15) asm volatile("cp.async.wait_group 1;" ::: "memory");
        else        asm volatile("cp.async.wait_group 0;" ::: "memory");
        __syncthreads();
#pragma unroll
        for (int ks = 0; ks < 2; ks++) {
            int kk = ks * 8;
            unsigned a[2][4];
#pragma unroll
            for (int mi = 0; mi < 2; mi++) {
                int rb = wm * 32 + mi * 16 + g;
                a[mi][0] = __float_as_uint(As[st][rb][kk + tg]);
                a[mi][1] = __float_as_uint(As[st][rb + 8][kk + tg]);
                a[mi][2] = __float_as_uint(As[st][rb][kk + tg + 4]);
                a[mi][3] = __float_as_uint(As[st][rb + 8][kk + tg + 4]);
            }
#pragma unroll
            for (int nt = 0; nt < 4; nt++) {
                int col = wn * 32 + nt * 8 + g;
                unsigned b0 = __float_as_uint(Bs[st][kk + tg][col]);
                unsigned b1 = __float_as_uint(Bs[st][kk + tg + 4][col]);
                mma_tf32(acc[0][nt], a[0], b0, b1);
                mma_tf32(acc[1][nt], a[1], b0, b1);
            }
        }
        __syncthreads();
    }
#undef GEMM1_ISSUE

    // epilogue: store h1 (bf16) + fused alpha1 (each warp = exactly 1 head)
    int head = (n0 >> 5) + wn;
    float ps[2][2] = {}, pd[2][2] = {};
#pragma unroll
    for (int mi = 0; mi < 2; mi++) {
        int r = m0 + wm * 32 + mi * 16 + g;
#pragma unroll
        for (int nt = 0; nt < 4; nt++) {
            int c = n0 + wn * 32 + nt * 8 + tg * 2;
            float w0s = a1s[c], w1s = a1s[c + 1];
            float w0d = a1d[c], w1d = a1d[c + 1];
            if (r < NN) {
                *reinterpret_cast<__nv_bfloat162*>(&g_h1[(size_t)r * C1 + c]) =
                    __floats2bfloat162_rn(acc[mi][nt][0], acc[mi][nt][1]);
            }
            if (r + 8 < NN) {
                *reinterpret_cast<__nv_bfloat162*>(&g_h1[(size_t)(r + 8) * C1 + c]) =
                    __floats2bfloat162_rn(acc[mi][nt][2], acc[mi][nt][3]);
            }
            ps[mi][0] += acc[mi][nt][0] * w0s + acc[mi][nt][1] * w1s;
            ps[mi][1] += acc[mi][nt][2] * w0s + acc[mi][nt][3] * w1s;
            pd[mi][0] += acc[mi][nt][0] * w0d + acc[mi][nt][1] * w1d;
            pd[mi][1] += acc[mi][nt][2] * w0d + acc[mi][nt][3] * w1d;
        }
    }
#pragma unroll
    for (int mi = 0; mi < 2; mi++)
#pragma unroll
        for (int rh = 0; rh < 2; rh++) {
            float s = ps[mi][rh], d = pd[mi][rh];
            s += __shfl_xor_sync(~0u, s, 1); s += __shfl_xor_sync(~0u, s, 2);
            d += __shfl_xor_sync(~0u, d, 1); d += __shfl_xor_sync(~0u, d, 2);
            if (tg == 0) {
                int r = m0 + wm * 32 + mi * 16 + g + rh * 8;
                if (r < NN) {
                    g_as1[r * HEADS + head] = s;
                    g_ad1[r * HEADS + head] = d;
                }
            }
        }
}

// ---------------- layer1 gather: warp per node (bf16 in, bf16 out) ----------
__global__ __launch_bounds__(256) void gather1(const float* __restrict__ b1) {
    int gw = (blockIdx.x * blockDim.x + threadIdx.x) >> 5;
    int l = threadIdx.x & 31;
    int ws = threadIdx.x >> 5;
    __shared__ float sad[8][8];
    __shared__ float sex[8][32 * 9];   // stride 9 -> conflict-free
    if (gw >= NN) return;
    int d = gw;
    int start = g_off[d];
    int deg = g_off[d + 1] - start;

    if (l < HEADS) sad[ws][l] = g_ad1[d * HEADS + l];
    __syncwarp();

    float acc[8];
#pragma unroll
    for (int j = 0; j < 8; j++) acc[j] = 0.f;
    float den = 0.f;
    int h = l >> 2;

    for (int base = 0; base < deg; base += 32) {
        int cnt = min(32, deg - base);
        int s_l = 0;
        if (l < cnt) {
            s_l = g_src[start + base + l];
            const float4* ap = reinterpret_cast<const float4*>(&g_as1[s_l * HEADS]);
            float4 v0 = ap[0];
            float4 v1 = ap[1];
            float* sx = &sex[ws][l * 9];
            sx[0] = lrelu_exp(v0.x + sad[ws][0]);
            sx[1] = lrelu_exp(v0.y + sad[ws][1]);
            sx[2] = lrelu_exp(v0.z + sad[ws][2]);
            sx[3] = lrelu_exp(v0.w + sad[ws][3]);
            sx[4] = lrelu_exp(v1.x + sad[ws][4]);
            sx[5] = lrelu_exp(v1.y + sad[ws][5]);
            sx[6] = lrelu_exp(v1.z + sad[ws][6]);
            sx[7] = lrelu_exp(v1.w + sad[ws][7]);
        }
        __syncwarp();
#pragma unroll 4
        for (int e = 0; e < cnt; e++) {
            int s = __shfl_sync(~0u, s_l, e);
            float ex = sex[ws][e * 9 + h];
            den += ex;
            uint4 rv = *reinterpret_cast<const uint4*>(&g_h1[(size_t)s * C1 + l * 8]);
            float2 f0 = __bfloat1622float2(*reinterpret_cast<__nv_bfloat162*>(&rv.x));
            float2 f1 = __bfloat1622float2(*reinterpret_cast<__nv_bfloat162*>(&rv.y));
            float2 f2 = __bfloat1622float2(*reinterpret_cast<__nv_bfloat162*>(&rv.z));
            float2 f3 = __bfloat1622float2(*reinterpret_cast<__nv_bfloat162*>(&rv.w));
            acc[0] += ex * f0.x; acc[1] += ex * f0.y;
            acc[2] += ex * f1.x; acc[3] += ex * f1.y;
            acc[4] += ex * f2.x; acc[5] += ex * f2.y;
            acc[6] += ex * f3.x; acc[7] += ex * f3.y;
        }
        __syncwarp();
    }

    float inv = 1.f / (den + 1e-16f);
    int chb = l * 8;
    float o[8];
#pragma unroll
    for (int j = 0; j < 8; j++) {
        float v = acc[j] * inv + b1[chb + j];
        o[j] = v > 0.f ? v : expm1f(v);
    }
    uint4 pk;
    pk.x = pack_bf2(o[0], o[1]);
    pk.y = pack_bf2(o[2], o[3]);
    pk.z = pack_bf2(o[4], o[5]);
    pk.w = pack_bf2(o[6], o[7]);
    *reinterpret_cast<uint4*>(&g_out1[(size_t)d * C1 + chb]) = pk;
}

// ---------------- GEMM2: h2 = out1 @ W2 (tf32, bf16 A in/out) + alpha2 ------
__global__ __launch_bounds__(256) void gemm2_kernel(const float* __restrict__ W2,
                                                    const float* __restrict__ a2s,
                                                    const float* __restrict__ a2d) {
    __shared__ float As[128][36];
    __shared__ float Bs[32][44];
    int tid = threadIdx.x;
    int lane = tid & 31, wid = tid >> 5;
    int g = lane >> 2, tg = lane & 3;
    int m0 = blockIdx.x * 128;

    float acc[5][4];
#pragma unroll
    for (int j = 0; j < 5; j++)
#pragma unroll
        for (int k = 0; k < 4; k++) acc[j][k] = 0.f;

    int a_r = tid >> 3;
    int a_c = (tid & 7) * 4;

    for (int k0 = 0; k0 < C1; k0 += 32) {
#pragma unroll
        for (int j = 0; j < 4; j++) {
            int r = a_r + 32 * j;
            int gm = m0 + r;
            float4 v = make_float4(0.f, 0.f, 0.f, 0.f);
            if (gm < NN) {
                uint2 rv = *reinterpret_cast<const uint2*>(&g_out1[(size_t)gm * C1 + k0 + a_c]);
                float2 f0 = __bfloat1622float2(*reinterpret_cast<__nv_bfloat162*>(&rv.x));
                float2 f1 = __bfloat1622float2(*reinterpret_cast<__nv_bfloat162*>(&rv.y));
                v = make_float4(f0.x, f0.y, f1.x, f1.y);
            }
            As[r][a_c + 0] = v.x;
            As[r][a_c + 1] = v.y;
            As[r][a_c + 2] = v.z;
            As[r][a_c + 3] = v.w;
        }
        for (int idx = tid; idx < 32 * OUTC; idx += 256) {
            int r = idx / OUTC, c = idx % OUTC;
            Bs[r][c] = __uint_as_float(f2tf32(W2[(size_t)(k0 + r) * OUTC + c]));
        }
        __syncthreads();
#pragma unroll
        for (int ks = 0; ks < 4; ks++) {
            int kk = ks * 8;
            unsigned a[4];
            int rb = wid * 16 + g;
            a[0] = __float_as_uint(As[rb][kk + tg]);
            a[1] = __float_as_uint(As[rb + 8][kk + tg]);
            a[2] = __float_as_uint(As[rb][kk + tg + 4]);
            a[3] = __float_as_uint(As[rb + 8][kk + tg + 4]);
#pragma unroll
            for (int nt = 0; nt < 5; nt++) {
                int col = nt * 8 + g;
                unsigned b0 = __float_as_uint(Bs[kk + tg][col]);
                unsigned b1r = __float_as_uint(Bs[kk + tg + 4][col]);
                mma_tf32(acc[nt], a, b0, b1r);
            }
        }
        __syncthreads();
    }
    int rlo = m0 + wid * 16 + g;
    int rhi = rlo + 8;
    float s_lo = 0.f, s_hi = 0.f, d_lo = 0.f, d_hi = 0.f;
#pragma unroll
    for (int nt = 0; nt < 5; nt++) {
        int c = nt * 8 + tg * 2;
        float w0s = a2s[c], w1s = a2s[c + 1];
        float w0d = a2d[c], w1d = a2d[c + 1];
        if (rlo < NN) {
            *reinterpret_cast<__nv_bfloat162*>(&g_h2[(size_t)rlo * OUTC + c]) =
                __floats2bfloat162_rn(acc[nt][0], acc[nt][1]);
        }
        if (rhi < NN) {
            *reinterpret_cast<__nv_bfloat162*>(&g_h2[(size_t)rhi * OUTC + c]) =
                __floats2bfloat162_rn(acc[nt][2], acc[nt][3]);
        }
        s_lo += acc[nt][0] * w0s + acc[nt][1] * w1s;
        s_hi += acc[nt][2] * w0s + acc[nt][3] * w1s;
        d_lo += acc[nt][0] * w0d + acc[nt][1] * w1d;
        d_hi += acc[nt][2] * w0d + acc[nt][3] * w1d;
    }
#pragma unroll
    for (int o = 1; o <= 2; o <<= 1) {
        s_lo += __shfl_xor_sync(~0u, s_lo, o);
        s_hi += __shfl_xor_sync(~0u, s_hi, o);
        d_lo += __shfl_xor_sync(~0u, d_lo, o);
        d_hi += __shfl_xor_sync(~0u, d_hi, o);
    }
    if (tg == 0) {
        if (rlo < NN) { g_as2[rlo] = s_lo; g_ad2[rlo] = d_lo; }
        if (rhi < NN) { g_as2[rhi] = s_hi; g_ad2[rhi] = d_hi; }
    }
}

// ---------------- layer2 gather: warp per node (bf16 h2), fused log_softmax --
__global__ __launch_bounds__(256) void gather2(const float* __restrict__ b2,
                                               float* __restrict__ out) {
    int gw = (blockIdx.x * blockDim.x + threadIdx.x) >> 5;
    int l = threadIdx.x & 31;
    if (gw >= NN) return;
    int d = gw;
    int start = g_off[d];
    int deg = g_off[d + 1] - start;

    float ad = g_ad2[d];
    float accx = 0.f, accy = 0.f, denp = 0.f;

    for (int base = 0; base < deg; base += 32) {
        int cnt = min(32, deg - base);
        int s_l = 0;
        float ex_l = 0.f;
        if (l < cnt) {
            s_l = g_src[start + base + l];
            ex_l = lrelu_exp(g_as2[s_l] + ad);
        }
        denp += ex_l;
#pragma unroll 4
        for (int e = 0; e < cnt; e++) {
            int s = __shfl_sync(~0u, s_l, e);
            float ex = __shfl_sync(~0u, ex_l, e);
            if (l < OUTC / 2) {
                __nv_bfloat162 hv = *reinterpret_cast<const __nv_bfloat162*>(
                    &g_h2[(size_t)s * OUTC + 2 * l]);
                float2 f = __bfloat1622float2(hv);
                accx += ex * f.x;
                accy += ex * f.y;
            }
        }
    }
    float den = denp;
#pragma unroll
    for (int o = 16; o; o >>= 1) den += __shfl_xor_sync(~0u, den, o);
    float inv = 1.f / (den + 1e-16f);

    bool act = (l < OUTC / 2);
    float v0 = act ? (accx * inv + b2[2 * l])     : -1e30f;
    float v1 = act ? (accy * inv + b2[2 * l + 1]) : -1e30f;
    float m = fmaxf(v0, v1);
#pragma unroll
    for (int o = 16; o; o >>= 1) m = fmaxf(m, __shfl_xor_sync(~0u, m, o));
    float sum = act ? (__expf(v0 - m) + __expf(v1 - m)) : 0.f;
#pragma unroll
    for (int o = 16; o; o >>= 1) sum += __shfl_xor_sync(~0u, sum, o);
    float lse = m + logf(sum);
    if (act) {
        float2 res = make_float2(v0 - lse, v1 - lse);
        *reinterpret_cast<float2*>(&out[(size_t)d * OUTC + 2 * l]) = res;
    }
}

// ---------------- launch --------------------------------------------------------
extern "C" void kernel_launch(void* const* d_in, const int* in_sizes, int n_in,
                              void* d_out, int out_size) {
    const float* x   = (const float*)d_in[0];
    const int*   ei  = (const int*)d_in[1];
    const float* W1  = (const float*)d_in[2];
    const float* a1s = (const float*)d_in[3];
    const float* a1d = (const float*)d_in[4];
    const float* b1  = (const float*)d_in[5];
    const float* W2  = (const float*)d_in[6];
    const float* a2s = (const float*)d_in[7];
    const float* a2d = (const float*)d_in[8];
    const float* b2  = (const float*)d_in[9];
    float*       out = (float*)d_out;

    // Side stream + events, created once on the first (non-captured) call.
    // Same GPU work is enqueued on every call; only host-side handles persist.
    static cudaStream_t s_csr = nullptr;
    static cudaEvent_t  ev_fork = nullptr, ev_join = nullptr;
    if (s_csr == nullptr) {
        cudaStreamCreateWithFlags(&s_csr, cudaStreamNonBlocking);
        cudaEventCreateWithFlags(&ev_fork, cudaEventDisableTiming);
        cudaEventCreateWithFlags(&ev_join, cudaEventDisableTiming);
    }

    // fork: CSR build runs concurrently with gemm1 (independent inputs)
    cudaEventRecord(ev_fork, 0);
    cudaStreamWaitEvent(s_csr, ev_fork, 0);

    deg_hist<<<(E0 + 255) / 256, 256, 0, s_csr>>>(ei);
    scan_kernel<<<1, 1024, 0, s_csr>>>();
    fill_csr<<<(E0 + 255) / 256, 256, 0, s_csr>>>(ei);
    cudaEventRecord(ev_join, s_csr);

    gemm1_kernel<<<dim3(2, (NN + 63) / 64), 256>>>(x, W1, a1s, a1d);

    // join: gather1 needs both CSR and gemm1 results
    cudaStreamWaitEvent(0, ev_join, 0);

    gather1<<<(NN * 32 + 255) / 256, 256>>>(b1);

    gemm2_kernel<<<(NN + 127) / 128, 256>>>(W2, a2s, a2d);

    gather2<<<(NN * 32 + 255) / 256, 256>>>(b2, out);
}

// round 16
// speedup vs baseline: 1.1104x; 1.0083x over previous
#include <cuda_runtime.h>
#include <cuda_bf16.h>

#define NN   20000
#define INCH 256
#define HEADS 8
#define HID  32
#define C1   256      // HEADS*HID
#define OUTC 40
#define E0   320000
#define ET   340000   // + self loops
#define NEG  0.2f

// ---------------- scratch (device globals; no allocation allowed) ----------
__device__ __nv_bfloat16 g_h1[NN * C1];    // x @ W1 (bf16)
__device__ float g_as1[NN * HEADS];
__device__ float g_ad1[NN * HEADS];
__device__ __nv_bfloat16 g_out1[NN * C1];  // elu(aggr + b1) (bf16)
__device__ __nv_bfloat16 g_h2[NN * OUTC];  // out1 @ W2 (bf16)
__device__ float g_as2[NN];
__device__ float g_ad2[NN];
__device__ int   g_deg[NN];                // zero-init at load; re-zeroed by scan
__device__ int   g_off[NN + 1];
__device__ int   g_cur[NN];
__device__ int   g_src[ET];                // CSR payload: src node per slot

// ---------------- helpers ---------------------------------------------------
__device__ __forceinline__ unsigned f2tf32(float f) {
    unsigned r;
    asm volatile("cvt.rna.tf32.f32 %0, %1;" : "=r"(r) : "f"(f));
    return r;
}
__device__ __forceinline__ void mma_tf32(float* c, const unsigned* a, unsigned b0, unsigned b1) {
    asm volatile(
        "mma.sync.aligned.m16n8k8.row.col.f32.tf32.tf32.f32 "
        "{%0,%1,%2,%3}, {%4,%5,%6,%7}, {%8,%9}, {%0,%1,%2,%3};"
        : "+f"(c[0]), "+f"(c[1]), "+f"(c[2]), "+f"(c[3])
        : "r"(a[0]), "r"(a[1]), "r"(a[2]), "r"(a[3]), "r"(b0), "r"(b1));
}
__device__ __forceinline__ float lrelu_exp(float v) {
    v = v > 0.f ? v : NEG * v;
    return __expf(v);
}
__device__ __forceinline__ unsigned pack_bf2(float a, float b) {
    __nv_bfloat162 t = __floats2bfloat162_rn(a, b);
    return *reinterpret_cast<unsigned*>(&t);
}
__device__ __forceinline__ void cp16(unsigned dst, const void* src, int nbytes) {
    asm volatile("cp.async.cg.shared.global [%0], [%1], 16, %2;"
                 :: "r"(dst), "l"(src), "r"(nbytes) : "memory");
}

// ---------------- CSR build --------------------------------------------------
__global__ void deg_hist(const int* __restrict__ ei) {
    int e = blockIdx.x * blockDim.x + threadIdx.x;
    if (e >= E0) return;
    atomicAdd(&g_deg[ei[E0 + e]], 1);
}

__global__ __launch_bounds__(1024) void scan_kernel() {
    __shared__ int wsum[32];
    __shared__ int carry_s;
    int tid = threadIdx.x;
    int lane = tid & 31, wid = tid >> 5;
    if (tid == 0) carry_s = 0;
    __syncthreads();
    for (int base = 0; base < NN; base += 1024) {
        int idx = base + tid;
        int v = 0;
        if (idx < NN) {
            v = g_deg[idx] + 1;     // +1 = self-loop
            g_deg[idx] = 0;          // reset for next replay
        }
        int x = v;
#pragma unroll
        for (int o = 1; o < 32; o <<= 1) {
            int y = __shfl_up_sync(~0u, x, o);
            if (lane >= o) x += y;
        }
        if (lane == 31) wsum[wid] = x;
        __syncthreads();
        if (wid == 0) {
            int w = wsum[lane];
#pragma unroll
            for (int o = 1; o < 32; o <<= 1) {
                int y = __shfl_up_sync(~0u, w, o);
                if (lane >= o) w += y;
            }
            wsum[lane] = w;
        }
        __syncthreads();
        int incl = x + (wid ? wsum[wid - 1] : 0);
        int excl = carry_s + incl - v;
        if (idx < NN) {
            g_off[idx] = excl;
            g_cur[idx] = excl + 1;
            g_src[excl] = idx;       // self-loop at slot 0
        }
        __syncthreads();
        if (tid == 0) carry_s += wsum[31];
        __syncthreads();
    }
    if (tid == 0) g_off[NN] = carry_s;
}

__global__ void fill_csr(const int* __restrict__ ei) {
    int e = blockIdx.x * blockDim.x + threadIdx.x;
    if (e >= E0) return;
    int s = ei[e];
    int d = ei[E0 + e];
    int pos = atomicAdd(&g_cur[d], 1);
    g_src[pos] = s;
}

// ---------------- GEMM1: h1 = x @ W1 (tf32, cp.async 3-stage) + alpha1 ------
// block tile 64x128, BK=16, 8 warps (2m x 4n), warp tile 32x32.
// 3-stage pipeline: ONE __syncthreads per K-tile, 2 cp.async groups in flight.
__global__ __launch_bounds__(256, 3) void gemm1_kernel(const float* __restrict__ x,
                                                       const float* __restrict__ W1,
                                                       const float* __restrict__ a1s,
                                                       const float* __restrict__ a1d) {
    __shared__ __align__(16) float As[3][64][20];    // [m][k], stride 20 conflict-free
    __shared__ __align__(16) float Bs[3][16][136];   // [k][n], stride 136 conflict-free
    int tid = threadIdx.x;
    int lane = tid & 31, wid = tid >> 5;
    int wm = wid & 1, wn = wid >> 1;      // 2 m-warps x 4 n-warps
    int g = lane >> 2, tg = lane & 3;
    int m0 = blockIdx.y * 64, n0 = blockIdx.x * 128;

    float acc[2][4][4];
#pragma unroll
    for (int i = 0; i < 2; i++)
#pragma unroll
        for (int j = 0; j < 4; j++)
#pragma unroll
            for (int k = 0; k < 4; k++) acc[i][j][k] = 0.f;

    int a_row = tid >> 2;            // 0..63
    int a_off = (tid & 3) * 4;       // float offset {0,4,8,12}
    int a_gm  = m0 + a_row;
    const float* a_src_base = &x[(size_t)min(a_gm, NN - 1) * INCH + a_off];
    int a_bytes = (a_gm < NN) ? 16 : 0;

#define GEMM1_ISSUE(t, st)                                                          \
    {                                                                               \
        int k0_ = (t) * 16;                                                         \
        cp16((unsigned)__cvta_generic_to_shared(&As[st][a_row][a_off]),             \
             a_src_base + k0_, a_bytes);                                            \
        _Pragma("unroll")                                                           \
        for (int j_ = 0; j_ < 2; j_++) {                                            \
            int c_ = tid + j_ * 256;                                                \
            int kr_ = c_ >> 5, ob_ = (c_ & 31) * 4;                                 \
            cp16((unsigned)__cvta_generic_to_shared(&Bs[st][kr_][ob_]),             \
                 &W1[(size_t)(k0_ + kr_) * C1 + n0 + ob_], 16);                     \
        }                                                                           \
        asm volatile("cp.async.commit_group;" ::: "memory");                        \
    }

    GEMM1_ISSUE(0, 0);
    GEMM1_ISSUE(1, 1);

#pragma unroll
    for (int t = 0; t < 16; t++) {
        int st = t % 3;
        if (t < 15) asm volatile("cp.async.wait_group 1;" ::: "memory");
        else        asm volatile("cp.async.wait_group 0;" ::: "memory");
        __syncthreads();   // orders: stage st ready; stage (t+2)%3 free for refill
        if (t + 2 < 16) { int sn = (t + 2) % 3; GEMM1_ISSUE(t + 2, sn); }
#pragma unroll
        for (int ks = 0; ks < 2; ks++) {
            int kk = ks * 8;
            unsigned a[2][4];
#pragma unroll
            for (int mi = 0; mi < 2; mi++) {
                int rb = wm * 32 + mi * 16 + g;
                a[mi][0] = __float_as_uint(As[st][rb][kk + tg]);
                a[mi][1] = __float_as_uint(As[st][rb + 8][kk + tg]);
                a[mi][2] = __float_as_uint(As[st][rb][kk + tg + 4]);
                a[mi][3] = __float_as_uint(As[st][rb + 8][kk + tg + 4]);
            }
#pragma unroll
            for (int nt = 0; nt < 4; nt++) {
                int col = wn * 32 + nt * 8 + g;
                unsigned b0 = __float_as_uint(Bs[st][kk + tg][col]);
                unsigned b1 = __float_as_uint(Bs[st][kk + tg + 4][col]);
                mma_tf32(acc[0][nt], a[0], b0, b1);
                mma_tf32(acc[1][nt], a[1], b0, b1);
            }
        }
    }
#undef GEMM1_ISSUE

    // epilogue: store h1 (bf16) + fused alpha1 (each warp = exactly 1 head)
    int head = (n0 >> 5) + wn;
    float ps[2][2] = {}, pd[2][2] = {};
#pragma unroll
    for (int mi = 0; mi < 2; mi++) {
        int r = m0 + wm * 32 + mi * 16 + g;
#pragma unroll
        for (int nt = 0; nt < 4; nt++) {
            int c = n0 + wn * 32 + nt * 8 + tg * 2;
            float w0s = a1s[c], w1s = a1s[c + 1];
            float w0d = a1d[c], w1d = a1d[c + 1];
            if (r < NN) {
                *reinterpret_cast<__nv_bfloat162*>(&g_h1[(size_t)r * C1 + c]) =
                    __floats2bfloat162_rn(acc[mi][nt][0], acc[mi][nt][1]);
            }
            if (r + 8 < NN) {
                *reinterpret_cast<__nv_bfloat162*>(&g_h1[(size_t)(r + 8) * C1 + c]) =
                    __floats2bfloat162_rn(acc[mi][nt][2], acc[mi][nt][3]);
            }
            ps[mi][0] += acc[mi][nt][0] * w0s + acc[mi][nt][1] * w1s;
            ps[mi][1] += acc[mi][nt][2] * w0s + acc[mi][nt][3] * w1s;
            pd[mi][0] += acc[mi][nt][0] * w0d + acc[mi][nt][1] * w1d;
            pd[mi][1] += acc[mi][nt][2] * w0d + acc[mi][nt][3] * w1d;
        }
    }
#pragma unroll
    for (int mi = 0; mi < 2; mi++)
#pragma unroll
        for (int rh = 0; rh < 2; rh++) {
            float s = ps[mi][rh], d = pd[mi][rh];
            s += __shfl_xor_sync(~0u, s, 1); s += __shfl_xor_sync(~0u, s, 2);
            d += __shfl_xor_sync(~0u, d, 1); d += __shfl_xor_sync(~0u, d, 2);
            if (tg == 0) {
                int r = m0 + wm * 32 + mi * 16 + g + rh * 8;
                if (r < NN) {
                    g_as1[r * HEADS + head] = s;
                    g_ad1[r * HEADS + head] = d;
                }
            }
        }
}

// ---------------- layer1 gather: warp per node (bf16 in, bf16 out) ----------
__global__ __launch_bounds__(256) void gather1(const float* __restrict__ b1) {
    int gw = (blockIdx.x * blockDim.x + threadIdx.x) >> 5;
    int l = threadIdx.x & 31;
    int ws = threadIdx.x >> 5;
    __shared__ float sad[8][8];
    __shared__ float sex[8][32 * 9];   // stride 9 -> conflict-free
    if (gw >= NN) return;
    int d = gw;
    int start = g_off[d];
    int deg = g_off[d + 1] - start;

    if (l < HEADS) sad[ws][l] = g_ad1[d * HEADS + l];
    __syncwarp();

    float acc[8];
#pragma unroll
    for (int j = 0; j < 8; j++) acc[j] = 0.f;
    float den = 0.f;
    int h = l >> 2;

    for (int base = 0; base < deg; base += 32) {
        int cnt = min(32, deg - base);
        int s_l = 0;
        if (l < cnt) {
            s_l = g_src[start + base + l];
            const float4* ap = reinterpret_cast<const float4*>(&g_as1[s_l * HEADS]);
            float4 v0 = ap[0];
            float4 v1 = ap[1];
            float* sx = &sex[ws][l * 9];
            sx[0] = lrelu_exp(v0.x + sad[ws][0]);
            sx[1] = lrelu_exp(v0.y + sad[ws][1]);
            sx[2] = lrelu_exp(v0.z + sad[ws][2]);
            sx[3] = lrelu_exp(v0.w + sad[ws][3]);
            sx[4] = lrelu_exp(v1.x + sad[ws][4]);
            sx[5] = lrelu_exp(v1.y + sad[ws][5]);
            sx[6] = lrelu_exp(v1.z + sad[ws][6]);
            sx[7] = lrelu_exp(v1.w + sad[ws][7]);
        }
        __syncwarp();
#pragma unroll 4
        for (int e = 0; e < cnt; e++) {
            int s = __shfl_sync(~0u, s_l, e);
            float ex = sex[ws][e * 9 + h];
            den += ex;
            uint4 rv = *reinterpret_cast<const uint4*>(&g_h1[(size_t)s * C1 + l * 8]);
            float2 f0 = __bfloat1622float2(*reinterpret_cast<__nv_bfloat162*>(&rv.x));
            float2 f1 = __bfloat1622float2(*reinterpret_cast<__nv_bfloat162*>(&rv.y));
            float2 f2 = __bfloat1622float2(*reinterpret_cast<__nv_bfloat162*>(&rv.z));
            float2 f3 = __bfloat1622float2(*reinterpret_cast<__nv_bfloat162*>(&rv.w));
            acc[0] += ex * f0.x; acc[1] += ex * f0.y;
            acc[2] += ex * f1.x; acc[3] += ex * f1.y;
            acc[4] += ex * f2.x; acc[5] += ex * f2.y;
            acc[6] += ex * f3.x; acc[7] += ex * f3.y;
        }
        __syncwarp();
    }

    float inv = 1.f / (den + 1e-16f);
    int chb = l * 8;
    float o[8];
#pragma unroll
    for (int j = 0; j < 8; j++) {
        float v = acc[j] * inv + b1[chb + j];
        o[j] = v > 0.f ? v : expm1f(v);
    }
    uint4 pk;
    pk.x = pack_bf2(o[0], o[1]);
    pk.y = pack_bf2(o[2], o[3]);
    pk.z = pack_bf2(o[4], o[5]);
    pk.w = pack_bf2(o[6], o[7]);
    *reinterpret_cast<uint4*>(&g_out1[(size_t)d * C1 + chb]) = pk;
}

// ---------------- GEMM2: h2 = out1 @ W2 (tf32, bf16 A in/out) + alpha2 ------
__global__ __launch_bounds__(256) void gemm2_kernel(const float* __restrict__ W2,
                                                    const float* __restrict__ a2s,
                                                    const float* __restrict__ a2d) {
    __shared__ float As[128][36];
    __shared__ float Bs[32][44];
    int tid = threadIdx.x;
    int lane = tid & 31, wid = tid >> 5;
    int g = lane >> 2, tg = lane & 3;
    int m0 = blockIdx.x * 128;

    float acc[5][4];
#pragma unroll
    for (int j = 0; j < 5; j++)
#pragma unroll
        for (int k = 0; k < 4; k++) acc[j][k] = 0.f;

    int a_r = tid >> 3;
    int a_c = (tid & 7) * 4;

    for (int k0 = 0; k0 < C1; k0 += 32) {
#pragma unroll
        for (int j = 0; j < 4; j++) {
            int r = a_r + 32 * j;
            int gm = m0 + r;
            float4 v = make_float4(0.f, 0.f, 0.f, 0.f);
            if (gm < NN) {
                uint2 rv = *reinterpret_cast<const uint2*>(&g_out1[(size_t)gm * C1 + k0 + a_c]);
                float2 f0 = __bfloat1622float2(*reinterpret_cast<__nv_bfloat162*>(&rv.x));
                float2 f1 = __bfloat1622float2(*reinterpret_cast<__nv_bfloat162*>(&rv.y));
                v = make_float4(f0.x, f0.y, f1.x, f1.y);
            }
            As[r][a_c + 0] = v.x;
            As[r][a_c + 1] = v.y;
            As[r][a_c + 2] = v.z;
            As[r][a_c + 3] = v.w;
        }
        for (int idx = tid; idx < 32 * OUTC; idx += 256) {
            int r = idx / OUTC, c = idx % OUTC;
            Bs[r][c] = __uint_as_float(f2tf32(W2[(size_t)(k0 + r) * OUTC + c]));
        }
        __syncthreads();
#pragma unroll
        for (int ks = 0; ks < 4; ks++) {
            int kk = ks * 8;
            unsigned a[4];
            int rb = wid * 16 + g;
            a[0] = __float_as_uint(As[rb][kk + tg]);
            a[1] = __float_as_uint(As[rb + 8][kk + tg]);
            a[2] = __float_as_uint(As[rb][kk + tg + 4]);
            a[3] = __float_as_uint(As[rb + 8][kk + tg + 4]);
#pragma unroll
            for (int nt = 0; nt < 5; nt++) {
                int col = nt * 8 + g;
                unsigned b0 = __float_as_uint(Bs[kk + tg][col]);
                unsigned b1r = __float_as_uint(Bs[kk + tg + 4][col]);
                mma_tf32(acc[nt], a, b0, b1r);
            }
        }
        __syncthreads();
    }
    int rlo = m0 + wid * 16 + g;
    int rhi = rlo + 8;
    float s_lo = 0.f, s_hi = 0.f, d_lo = 0.f, d_hi = 0.f;
#pragma unroll
    for (int nt = 0; nt < 5; nt++) {
        int c = nt * 8 + tg * 2;
        float w0s = a2s[c], w1s = a2s[c + 1];
        float w0d = a2d[c], w1d = a2d[c + 1];
        if (rlo < NN) {
            *reinterpret_cast<__nv_bfloat162*>(&g_h2[(size_t)rlo * OUTC + c]) =
                __floats2bfloat162_rn(acc[nt][0], acc[nt][1]);
        }
        if (rhi < NN) {
            *reinterpret_cast<__nv_bfloat162*>(&g_h2[(size_t)rhi * OUTC + c]) =
                __floats2bfloat162_rn(acc[nt][2], acc[nt][3]);
        }
        s_lo += acc[nt][0] * w0s + acc[nt][1] * w1s;
        s_hi += acc[nt][2] * w0s + acc[nt][3] * w1s;
        d_lo += acc[nt][0] * w0d + acc[nt][1] * w1d;
        d_hi += acc[nt][2] * w0d + acc[nt][3] * w1d;
    }
#pragma unroll
    for (int o = 1; o <= 2; o <<= 1) {
        s_lo += __shfl_xor_sync(~0u, s_lo, o);
        s_hi += __shfl_xor_sync(~0u, s_hi, o);
        d_lo += __shfl_xor_sync(~0u, d_lo, o);
        d_hi += __shfl_xor_sync(~0u, d_hi, o);
    }
    if (tg == 0) {
        if (rlo < NN) { g_as2[rlo] = s_lo; g_ad2[rlo] = d_lo; }
        if (rhi < NN) { g_as2[rhi] = s_hi; g_ad2[rhi] = d_hi; }
    }
}

// ---------------- layer2 gather: warp per node (bf16 h2), fused log_softmax --
__global__ __launch_bounds__(256) void gather2(const float* __restrict__ b2,
                                               float* __restrict__ out) {
    int gw = (blockIdx.x * blockDim.x + threadIdx.x) >> 5;
    int l = threadIdx.x & 31;
    if (gw >= NN) return;
    int d = gw;
    int start = g_off[d];
    int deg = g_off[d + 1] - start;

    float ad = g_ad2[d];
    float accx = 0.f, accy = 0.f, denp = 0.f;

    for (int base = 0; base < deg; base += 32) {
        int cnt = min(32, deg - base);
        int s_l = 0;
        float ex_l = 0.f;
        if (l < cnt) {
            s_l = g_src[start + base + l];
            ex_l = lrelu_exp(g_as2[s_l] + ad);
        }
        denp += ex_l;
#pragma unroll 4
        for (int e = 0; e < cnt; e++) {
            int s = __shfl_sync(~0u, s_l, e);
            float ex = __shfl_sync(~0u, ex_l, e);
            if (l < OUTC / 2) {
                __nv_bfloat162 hv = *reinterpret_cast<const __nv_bfloat162*>(
                    &g_h2[(size_t)s * OUTC + 2 * l]);
                float2 f = __bfloat1622float2(hv);
                accx += ex * f.x;
                accy += ex * f.y;
            }
        }
    }
    float den = denp;
#pragma unroll
    for (int o = 16; o; o >>= 1) den += __shfl_xor_sync(~0u, den, o);
    float inv = 1.f / (den + 1e-16f);

    bool act = (l < OUTC / 2);
    float v0 = act ? (accx * inv + b2[2 * l])     : -1e30f;
    float v1 = act ? (accy * inv + b2[2 * l + 1]) : -1e30f;
    float m = fmaxf(v0, v1);
#pragma unroll
    for (int o = 16; o; o >>= 1) m = fmaxf(m, __shfl_xor_sync(~0u, m, o));
    float sum = act ? (__expf(v0 - m) + __expf(v1 - m)) : 0.f;
#pragma unroll
    for (int o = 16; o; o >>= 1) sum += __shfl_xor_sync(~0u, sum, o);
    float lse = m + logf(sum);
    if (act) {
        float2 res = make_float2(v0 - lse, v1 - lse);
        *reinterpret_cast<float2*>(&out[(size_t)d * OUTC + 2 * l]) = res;
    }
}

// ---------------- launch --------------------------------------------------------
extern "C" void kernel_launch(void* const* d_in, const int* in_sizes, int n_in,
                              void* d_out, int out_size) {
    const float* x   = (const float*)d_in[0];
    const int*   ei  = (const int*)d_in[1];
    const float* W1  = (const float*)d_in[2];
    const float* a1s = (const float*)d_in[3];
    const float* a1d = (const float*)d_in[4];
    const float* b1  = (const float*)d_in[5];
    const float* W2  = (const float*)d_in[6];
    const float* a2s = (const float*)d_in[7];
    const float* a2d = (const float*)d_in[8];
    const float* b2  = (const float*)d_in[9];
    float*       out = (float*)d_out;

    static cudaStream_t s_csr = nullptr;
    static cudaEvent_t  ev_fork = nullptr, ev_join = nullptr;
    if (s_csr == nullptr) {
        cudaStreamCreateWithFlags(&s_csr, cudaStreamNonBlocking);
        cudaEventCreateWithFlags(&ev_fork, cudaEventDisableTiming);
        cudaEventCreateWithFlags(&ev_join, cudaEventDisableTiming);
    }

    // fork: CSR build runs concurrently with gemm1 (independent inputs)
    cudaEventRecord(ev_fork, 0);
    cudaStreamWaitEvent(s_csr, ev_fork, 0);

    deg_hist<<<(E0 + 255) / 256, 256, 0, s_csr>>>(ei);
    scan_kernel<<<1, 1024, 0, s_csr>>>();
    fill_csr<<<(E0 + 255) / 256, 256, 0, s_csr>>>(ei);
    cudaEventRecord(ev_join, s_csr);

    gemm1_kernel<<<dim3(2, (NN + 63) / 64), 256>>>(x, W1, a1s, a1d);

    // join: gather1 needs both CSR and gemm1 results
    cudaStreamWaitEvent(0, ev_join, 0);

    gather1<<<(NN * 32 + 255) / 256, 256>>>(b1);

    gemm2_kernel<<<(NN + 127) / 128, 256>>>(W2, a2s, a2d);

    gather2<<<(NN * 32 + 255) / 256, 256>>>(b2, out);
}

// round 17
// speedup vs baseline: 1.2537x; 1.1290x over previous
#include <cuda_runtime.h>
#include <cuda_bf16.h>

#define NN   20000
#define INCH 256
#define HEADS 8
#define HID  32
#define C1   256      // HEADS*HID
#define OUTC 40
#define E0   320000
#define ET   340000   // + self loops
#define NEG  0.2f

// ---------------- scratch (device globals; no allocation allowed) ----------
__device__ __nv_bfloat16 g_h1[NN * C1];    // x @ W1 (bf16)
__device__ float g_as1[NN * HEADS];
__device__ float g_ad1[NN * HEADS];
__device__ __nv_bfloat16 g_out1[NN * C1];  // elu(aggr + b1) (bf16)
__device__ __nv_bfloat16 g_h2[NN * OUTC];  // out1 @ W2 (bf16)
__device__ float g_as2[NN];
__device__ float g_ad2[NN];
__device__ int   g_deg[NN];                // zero-init at load; re-zeroed by scan
__device__ int   g_off[NN + 1];
__device__ int   g_cur[NN];
__device__ int   g_src[ET];                // CSR payload: src node per slot

// ---------------- helpers ---------------------------------------------------
__device__ __forceinline__ void mma_tf32(float* c, const unsigned* a, unsigned b0, unsigned b1) {
    asm volatile(
        "mma.sync.aligned.m16n8k8.row.col.f32.tf32.tf32.f32 "
        "{%0,%1,%2,%3}, {%4,%5,%6,%7}, {%8,%9}, {%0,%1,%2,%3};"
        : "+f"(c[0]), "+f"(c[1]), "+f"(c[2]), "+f"(c[3])
        : "r"(a[0]), "r"(a[1]), "r"(a[2]), "r"(a[3]), "r"(b0), "r"(b1));
}
__device__ __forceinline__ void mma_bf16(float* c, const unsigned* a, unsigned b0, unsigned b1) {
    asm volatile(
        "mma.sync.aligned.m16n8k16.row.col.f32.bf16.bf16.f32 "
        "{%0,%1,%2,%3}, {%4,%5,%6,%7}, {%8,%9}, {%0,%1,%2,%3};"
        : "+f"(c[0]), "+f"(c[1]), "+f"(c[2]), "+f"(c[3])
        : "r"(a[0]), "r"(a[1]), "r"(a[2]), "r"(a[3]), "r"(b0), "r"(b1));
}
__device__ __forceinline__ float lrelu_exp(float v) {
    v = v > 0.f ? v : NEG * v;
    return __expf(v);
}
__device__ __forceinline__ unsigned pack_bf2(float a, float b) {
    __nv_bfloat162 t = __floats2bfloat162_rn(a, b);
    return *reinterpret_cast<unsigned*>(&t);
}
__device__ __forceinline__ void cp16(unsigned dst, const void* src, int nbytes) {
    asm volatile("cp.async.cg.shared.global [%0], [%1], 16, %2;"
                 :: "r"(dst), "l"(src), "r"(nbytes) : "memory");
}

// ---------------- CSR build --------------------------------------------------
__global__ void deg_hist(const int* __restrict__ ei) {
    int e = blockIdx.x * blockDim.x + threadIdx.x;
    if (e >= E0) return;
    atomicAdd(&g_deg[ei[E0 + e]], 1);
}

__global__ __launch_bounds__(1024) void scan_kernel() {
    __shared__ int wsum[32];
    __shared__ int carry_s;
    int tid = threadIdx.x;
    int lane = tid & 31, wid = tid >> 5;
    if (tid == 0) carry_s = 0;
    __syncthreads();
    for (int base = 0; base < NN; base += 1024) {
        int idx = base + tid;
        int v = 0;
        if (idx < NN) {
            v = g_deg[idx] + 1;     // +1 = self-loop
            g_deg[idx] = 0;          // reset for next replay
        }
        int x = v;
#pragma unroll
        for (int o = 1; o < 32; o <<= 1) {
            int y = __shfl_up_sync(~0u, x, o);
            if (lane >= o) x += y;
        }
        if (lane == 31) wsum[wid] = x;
        __syncthreads();
        if (wid == 0) {
            int w = wsum[lane];
#pragma unroll
            for (int o = 1; o < 32; o <<= 1) {
                int y = __shfl_up_sync(~0u, w, o);
                if (lane >= o) w += y;
            }
            wsum[lane] = w;
        }
        __syncthreads();
        int incl = x + (wid ? wsum[wid - 1] : 0);
        int excl = carry_s + incl - v;
        if (idx < NN) {
            g_off[idx] = excl;
            g_cur[idx] = excl + 1;
            g_src[excl] = idx;       // self-loop at slot 0
        }
        __syncthreads();
        if (tid == 0) carry_s += wsum[31];
        __syncthreads();
    }
    if (tid == 0) g_off[NN] = carry_s;
}

__global__ void fill_csr(const int* __restrict__ ei) {
    int e = blockIdx.x * blockDim.x + threadIdx.x;
    if (e >= E0) return;
    int s = ei[e];
    int d = ei[E0 + e];
    int pos = atomicAdd(&g_cur[d], 1);
    g_src[pos] = s;
}

// ---------------- GEMM1: h1 = x @ W1 (tf32, cp.async 3-stage) + alpha1 ------
__global__ __launch_bounds__(256, 3) void gemm1_kernel(const float* __restrict__ x,
                                                       const float* __restrict__ W1,
                                                       const float* __restrict__ a1s,
                                                       const float* __restrict__ a1d) {
    __shared__ __align__(16) float As[3][64][20];    // [m][k], stride 20 conflict-free
    __shared__ __align__(16) float Bs[3][16][136];   // [k][n], stride 136 conflict-free
    int tid = threadIdx.x;
    int lane = tid & 31, wid = tid >> 5;
    int wm = wid & 1, wn = wid >> 1;      // 2 m-warps x 4 n-warps
    int g = lane >> 2, tg = lane & 3;
    int m0 = blockIdx.y * 64, n0 = blockIdx.x * 128;

    float acc[2][4][4];
#pragma unroll
    for (int i = 0; i < 2; i++)
#pragma unroll
        for (int j = 0; j < 4; j++)
#pragma unroll
            for (int k = 0; k < 4; k++) acc[i][j][k] = 0.f;

    int a_row = tid >> 2;            // 0..63
    int a_off = (tid & 3) * 4;       // float offset {0,4,8,12}
    int a_gm  = m0 + a_row;
    const float* a_src_base = &x[(size_t)min(a_gm, NN - 1) * INCH + a_off];
    int a_bytes = (a_gm < NN) ? 16 : 0;

#define GEMM1_ISSUE(t, st)                                                          \
    {                                                                               \
        int k0_ = (t) * 16;                                                         \
        cp16((unsigned)__cvta_generic_to_shared(&As[st][a_row][a_off]),             \
             a_src_base + k0_, a_bytes);                                            \
        _Pragma("unroll")                                                           \
        for (int j_ = 0; j_ < 2; j_++) {                                            \
            int c_ = tid + j_ * 256;                                                \
            int kr_ = c_ >> 5, ob_ = (c_ & 31) * 4;                                 \
            cp16((unsigned)__cvta_generic_to_shared(&Bs[st][kr_][ob_]),             \
                 &W1[(size_t)(k0_ + kr_) * C1 + n0 + ob_], 16);                     \
        }                                                                           \
        asm volatile("cp.async.commit_group;" ::: "memory");                        \
    }

    GEMM1_ISSUE(0, 0);
    GEMM1_ISSUE(1, 1);

#pragma unroll
    for (int t = 0; t < 16; t++) {
        int st = t % 3;
        if (t < 15) asm volatile("cp.async.wait_group 1;" ::: "memory");
        else        asm volatile("cp.async.wait_group 0;" ::: "memory");
        __syncthreads();   // orders: stage st ready; stage (t+2)%3 free for refill
        if (t + 2 < 16) { int sn = (t + 2) % 3; GEMM1_ISSUE(t + 2, sn); }
#pragma unroll
        for (int ks = 0; ks < 2; ks++) {
            int kk = ks * 8;
            unsigned a[2][4];
#pragma unroll
            for (int mi = 0; mi < 2; mi++) {
                int rb = wm * 32 + mi * 16 + g;
                a[mi][0] = __float_as_uint(As[st][rb][kk + tg]);
                a[mi][1] = __float_as_uint(As[st][rb + 8][kk + tg]);
                a[mi][2] = __float_as_uint(As[st][rb][kk + tg + 4]);
                a[mi][3] = __float_as_uint(As[st][rb + 8][kk + tg + 4]);
            }
#pragma unroll
            for (int nt = 0; nt < 4; nt++) {
                int col = wn * 32 + nt * 8 + g;
                unsigned b0 = __float_as_uint(Bs[st][kk + tg][col]);
                unsigned b1 = __float_as_uint(Bs[st][kk + tg + 4][col]);
                mma_tf32(acc[0][nt], a[0], b0, b1);
                mma_tf32(acc[1][nt], a[1], b0, b1);
            }
        }
    }
#undef GEMM1_ISSUE

    // epilogue: store h1 (bf16) + fused alpha1 (each warp = exactly 1 head)
    int head = (n0 >> 5) + wn;
    float ps[2][2] = {}, pd[2][2] = {};
#pragma unroll
    for (int mi = 0; mi < 2; mi++) {
        int r = m0 + wm * 32 + mi * 16 + g;
#pragma unroll
        for (int nt = 0; nt < 4; nt++) {
            int c = n0 + wn * 32 + nt * 8 + tg * 2;
            float w0s = a1s[c], w1s = a1s[c + 1];
            float w0d = a1d[c], w1d = a1d[c + 1];
            if (r < NN) {
                *reinterpret_cast<__nv_bfloat162*>(&g_h1[(size_t)r * C1 + c]) =
                    __floats2bfloat162_rn(acc[mi][nt][0], acc[mi][nt][1]);
            }
            if (r + 8 < NN) {
                *reinterpret_cast<__nv_bfloat162*>(&g_h1[(size_t)(r + 8) * C1 + c]) =
                    __floats2bfloat162_rn(acc[mi][nt][2], acc[mi][nt][3]);
            }
            ps[mi][0] += acc[mi][nt][0] * w0s + acc[mi][nt][1] * w1s;
            ps[mi][1] += acc[mi][nt][2] * w0s + acc[mi][nt][3] * w1s;
            pd[mi][0] += acc[mi][nt][0] * w0d + acc[mi][nt][1] * w1d;
            pd[mi][1] += acc[mi][nt][2] * w0d + acc[mi][nt][3] * w1d;
        }
    }
#pragma unroll
    for (int mi = 0; mi < 2; mi++)
#pragma unroll
        for (int rh = 0; rh < 2; rh++) {
            float s = ps[mi][rh], d = pd[mi][rh];
            s += __shfl_xor_sync(~0u, s, 1); s += __shfl_xor_sync(~0u, s, 2);
            d += __shfl_xor_sync(~0u, d, 1); d += __shfl_xor_sync(~0u, d, 2);
            if (tg == 0) {
                int r = m0 + wm * 32 + mi * 16 + g + rh * 8;
                if (r < NN) {
                    g_as1[r * HEADS + head] = s;
                    g_ad1[r * HEADS + head] = d;
                }
            }
        }
}

// ---------------- layer1 gather: warp per node (bf16 in, bf16 out) ----------
__global__ __launch_bounds__(256) void gather1(const float* __restrict__ b1) {
    int gw = (blockIdx.x * blockDim.x + threadIdx.x) >> 5;
    int l = threadIdx.x & 31;
    int ws = threadIdx.x >> 5;
    __shared__ float sad[8][8];
    __shared__ float sex[8][32 * 9];   // stride 9 -> conflict-free
    if (gw >= NN) return;
    int d = gw;
    int start = g_off[d];
    int deg = g_off[d + 1] - start;

    if (l < HEADS) sad[ws][l] = g_ad1[d * HEADS + l];
    __syncwarp();

    float acc[8];
#pragma unroll
    for (int j = 0; j < 8; j++) acc[j] = 0.f;
    float den = 0.f;
    int h = l >> 2;

    for (int base = 0; base < deg; base += 32) {
        int cnt = min(32, deg - base);
        int s_l = 0;
        if (l < cnt) {
            s_l = g_src[start + base + l];
            const float4* ap = reinterpret_cast<const float4*>(&g_as1[s_l * HEADS]);
            float4 v0 = ap[0];
            float4 v1 = ap[1];
            float* sx = &sex[ws][l * 9];
            sx[0] = lrelu_exp(v0.x + sad[ws][0]);
            sx[1] = lrelu_exp(v0.y + sad[ws][1]);
            sx[2] = lrelu_exp(v0.z + sad[ws][2]);
            sx[3] = lrelu_exp(v0.w + sad[ws][3]);
            sx[4] = lrelu_exp(v1.x + sad[ws][4]);
            sx[5] = lrelu_exp(v1.y + sad[ws][5]);
            sx[6] = lrelu_exp(v1.z + sad[ws][6]);
            sx[7] = lrelu_exp(v1.w + sad[ws][7]);
        }
        __syncwarp();
#pragma unroll 4
        for (int e = 0; e < cnt; e++) {
            int s = __shfl_sync(~0u, s_l, e);
            float ex = sex[ws][e * 9 + h];
            den += ex;
            uint4 rv = *reinterpret_cast<const uint4*>(&g_h1[(size_t)s * C1 + l * 8]);
            float2 f0 = __bfloat1622float2(*reinterpret_cast<__nv_bfloat162*>(&rv.x));
            float2 f1 = __bfloat1622float2(*reinterpret_cast<__nv_bfloat162*>(&rv.y));
            float2 f2 = __bfloat1622float2(*reinterpret_cast<__nv_bfloat162*>(&rv.z));
            float2 f3 = __bfloat1622float2(*reinterpret_cast<__nv_bfloat162*>(&rv.w));
            acc[0] += ex * f0.x; acc[1] += ex * f0.y;
            acc[2] += ex * f1.x; acc[3] += ex * f1.y;
            acc[4] += ex * f2.x; acc[5] += ex * f2.y;
            acc[6] += ex * f3.x; acc[7] += ex * f3.y;
        }
        __syncwarp();
    }

    float inv = 1.f / (den + 1e-16f);
    int chb = l * 8;
    float o[8];
#pragma unroll
    for (int j = 0; j < 8; j++) {
        float v = acc[j] * inv + b1[chb + j];
        o[j] = v > 0.f ? v : expm1f(v);
    }
    uint4 pk;
    pk.x = pack_bf2(o[0], o[1]);
    pk.y = pack_bf2(o[2], o[3]);
    pk.z = pack_bf2(o[4], o[5]);
    pk.w = pack_bf2(o[6], o[7]);
    *reinterpret_cast<uint4*>(&g_out1[(size_t)d * C1 + chb]) = pk;
}

// ---------------- GEMM2: h2 = out1 @ W2 (bf16 MMA, cp.async A, resident B) --
// block tile 128x40, BK=32, 8 warps (16 rows each); W2 preloaded whole as
// Bn[n][k] bf16 (stride 264 -> conflict-free); out1 cp.async'd directly (bf16).
__global__ __launch_bounds__(256) void gemm2_kernel(const float* __restrict__ W2,
                                                    const float* __restrict__ a2s,
                                                    const float* __restrict__ a2d) {
    __shared__ __align__(16) __nv_bfloat16 As[2][128][40];   // stride 40 bf16 = 20 uint
    __shared__ __align__(16) __nv_bfloat16 Bn[OUTC][264];    // [n][k], full K resident
    int tid = threadIdx.x;
    int lane = tid & 31, wid = tid >> 5;
    int g = lane >> 2, tg = lane & 3;
    int m0 = blockIdx.x * 128;

    // one-time B preload: W2 [k][n] fp32 -> Bn [n][k] bf16 (coalesced gmem reads)
    for (int idx = tid; idx < C1 * OUTC; idx += 256) {
        int k = idx / OUTC, n = idx % OUTC;
        Bn[n][k] = __float2bfloat16(W2[idx]);
    }

    float acc[5][4];
#pragma unroll
    for (int j = 0; j < 5; j++)
#pragma unroll
        for (int k = 0; k < 4; k++) acc[j][k] = 0.f;

    // A cp.async: per tile 128 rows x 64B; thread -> row tid>>1, chunks 2*(tid&1)+{0,1}
    int a_row = tid >> 1;
    int a_c0  = (tid & 1) * 16;      // bf16 offset of first chunk
    int a_gm  = m0 + a_row;
    const __nv_bfloat16* a_src = &g_out1[(size_t)min(a_gm, NN - 1) * C1];
    int a_bytes = (a_gm < NN) ? 16 : 0;

#define GEMM2_ISSUE(t, st)                                                           \
    {                                                                                \
        int k0_ = (t) * 32;                                                          \
        cp16((unsigned)__cvta_generic_to_shared(&As[st][a_row][a_c0]),               \
             a_src + k0_ + a_c0, a_bytes);                                           \
        cp16((unsigned)__cvta_generic_to_shared(&As[st][a_row][a_c0 + 8]),           \
             a_src + k0_ + a_c0 + 8, a_bytes);                                       \
        asm volatile("cp.async.commit_group;" ::: "memory");                         \
    }

    GEMM2_ISSUE(0, 0);
    __syncthreads();   // also covers Bn preload visibility

#pragma unroll
    for (int t = 0; t < 8; t++) {
        int st = t & 1;
        if (t + 1 < 8) GEMM2_ISSUE(t + 1, st ^ 1);
        if (t + 1 < 8) asm volatile("cp.async.wait_group 1;" ::: "memory");
        else           asm volatile("cp.async.wait_group 0;" ::: "memory");
        __syncthreads();
        int rb = wid * 16 + g;
#pragma unroll
        for (int ks = 0; ks < 2; ks++) {
            int kk = ks * 16;
            unsigned a[4];
            a[0] = *reinterpret_cast<const unsigned*>(&As[st][rb][kk + 2 * tg]);
            a[1] = *reinterpret_cast<const unsigned*>(&As[st][rb + 8][kk + 2 * tg]);
            a[2] = *reinterpret_cast<const unsigned*>(&As[st][rb][kk + 2 * tg + 8]);
            a[3] = *reinterpret_cast<const unsigned*>(&As[st][rb + 8][kk + 2 * tg + 8]);
            int kt = t * 32 + kk;
#pragma unroll
            for (int nt = 0; nt < 5; nt++) {
                int col = nt * 8 + g;
                unsigned b0 = *reinterpret_cast<const unsigned*>(&Bn[col][kt + 2 * tg]);
                unsigned b1 = *reinterpret_cast<const unsigned*>(&Bn[col][kt + 2 * tg + 8]);
                mma_bf16(acc[nt], a, b0, b1);
            }
        }
        __syncthreads();
    }
#undef GEMM2_ISSUE

    int rlo = m0 + wid * 16 + g;
    int rhi = rlo + 8;
    float s_lo = 0.f, s_hi = 0.f, d_lo = 0.f, d_hi = 0.f;
#pragma unroll
    for (int nt = 0; nt < 5; nt++) {
        int c = nt * 8 + tg * 2;
        float w0s = a2s[c], w1s = a2s[c + 1];
        float w0d = a2d[c], w1d = a2d[c + 1];
        if (rlo < NN) {
            *reinterpret_cast<__nv_bfloat162*>(&g_h2[(size_t)rlo * OUTC + c]) =
                __floats2bfloat162_rn(acc[nt][0], acc[nt][1]);
        }
        if (rhi < NN) {
            *reinterpret_cast<__nv_bfloat162*>(&g_h2[(size_t)rhi * OUTC + c]) =
                __floats2bfloat162_rn(acc[nt][2], acc[nt][3]);
        }
        s_lo += acc[nt][0] * w0s + acc[nt][1] * w1s;
        s_hi += acc[nt][2] * w0s + acc[nt][3] * w1s;
        d_lo += acc[nt][0] * w0d + acc[nt][1] * w1d;
        d_hi += acc[nt][2] * w0d + acc[nt][3] * w1d;
    }
#pragma unroll
    for (int o = 1; o <= 2; o <<= 1) {
        s_lo += __shfl_xor_sync(~0u, s_lo, o);
        s_hi += __shfl_xor_sync(~0u, s_hi, o);
        d_lo += __shfl_xor_sync(~0u, d_lo, o);
        d_hi += __shfl_xor_sync(~0u, d_hi, o);
    }
    if (tg == 0) {
        if (rlo < NN) { g_as2[rlo] = s_lo; g_ad2[rlo] = d_lo; }
        if (rhi < NN) { g_as2[rhi] = s_hi; g_ad2[rhi] = d_hi; }
    }
}

// ---------------- layer2 gather: warp per node (bf16 h2), fused log_softmax --
__global__ __launch_bounds__(256) void gather2(const float* __restrict__ b2,
                                               float* __restrict__ out) {
    int gw = (blockIdx.x * blockDim.x + threadIdx.x) >> 5;
    int l = threadIdx.x & 31;
    if (gw >= NN) return;
    int d = gw;
    int start = g_off[d];
    int deg = g_off[d + 1] - start;

    float ad = g_ad2[d];
    float accx = 0.f, accy = 0.f, denp = 0.f;

    for (int base = 0; base < deg; base += 32) {
        int cnt = min(32, deg - base);
        int s_l = 0;
        float ex_l = 0.f;
        if (l < cnt) {
            s_l = g_src[start + base + l];
            ex_l = lrelu_exp(g_as2[s_l] + ad);
        }
        denp += ex_l;
#pragma unroll 4
        for (int e = 0; e < cnt; e++) {
            int s = __shfl_sync(~0u, s_l, e);
            float ex = __shfl_sync(~0u, ex_l, e);
            if (l < OUTC / 2) {
                __nv_bfloat162 hv = *reinterpret_cast<const __nv_bfloat162*>(
                    &g_h2[(size_t)s * OUTC + 2 * l]);
                float2 f = __bfloat1622float2(hv);
                accx += ex * f.x;
                accy += ex * f.y;
            }
        }
    }
    float den = denp;
#pragma unroll
    for (int o = 16; o; o >>= 1) den += __shfl_xor_sync(~0u, den, o);
    float inv = 1.f / (den + 1e-16f);

    bool act = (l < OUTC / 2);
    float v0 = act ? (accx * inv + b2[2 * l])     : -1e30f;
    float v1 = act ? (accy * inv + b2[2 * l + 1]) : -1e30f;
    float m = fmaxf(v0, v1);
#pragma unroll
    for (int o = 16; o; o >>= 1) m = fmaxf(m, __shfl_xor_sync(~0u, m, o));
    float sum = act ? (__expf(v0 - m) + __expf(v1 - m)) : 0.f;
#pragma unroll
    for (int o = 16; o; o >>= 1) sum += __shfl_xor_sync(~0u, sum, o);
    float lse = m + logf(sum);
    if (act) {
        float2 res = make_float2(v0 - lse, v1 - lse);
        *reinterpret_cast<float2*>(&out[(size_t)d * OUTC + 2 * l]) = res;
    }
}

// ---------------- launch --------------------------------------------------------
extern "C" void kernel_launch(void* const* d_in, const int* in_sizes, int n_in,
                              void* d_out, int out_size) {
    const float* x   = (const float*)d_in[0];
    const int*   ei  = (const int*)d_in[1];
    const float* W1  = (const float*)d_in[2];
    const float* a1s = (const float*)d_in[3];
    const float* a1d = (const float*)d_in[4];
    const float* b1  = (const float*)d_in[5];
    const float* W2  = (const float*)d_in[6];
    const float* a2s = (const float*)d_in[7];
    const float* a2d = (const float*)d_in[8];
    const float* b2  = (const float*)d_in[9];
    float*       out = (float*)d_out;

    static cudaStream_t s_csr = nullptr;
    static cudaEvent_t  ev_fork = nullptr, ev_join = nullptr;
    if (s_csr == nullptr) {
        cudaStreamCreateWithFlags(&s_csr, cudaStreamNonBlocking);
        cudaEventCreateWithFlags(&ev_fork, cudaEventDisableTiming);
        cudaEventCreateWithFlags(&ev_join, cudaEventDisableTiming);
    }

    // fork: CSR build runs concurrently with gemm1 (independent inputs)
    cudaEventRecord(ev_fork, 0);
    cudaStreamWaitEvent(s_csr, ev_fork, 0);

    deg_hist<<<(E0 + 255) / 256, 256, 0, s_csr>>>(ei);
    scan_kernel<<<1, 1024, 0, s_csr>>>();
    fill_csr<<<(E0 + 255) / 256, 256, 0, s_csr>>>(ei);
    cudaEventRecord(ev_join, s_csr);

    gemm1_kernel<<<dim3(2, (NN + 63) / 64), 256>>>(x, W1, a1s, a1d);

    // join: gather1 needs both CSR and gemm1 results
    cudaStreamWaitEvent(0, ev_join, 0);

    gather1<<<(NN * 32 + 255) / 256, 256>>>(b1);

    gemm2_kernel<<<(NN + 127) / 128, 256>>>(W2, a2s, a2d);

    gather2<<<(NN * 32 + 255) / 256, 256>>>(b2, out);
}